// round 13
// baseline (speedup 1.0000x reference)
#include <cuda_runtime.h>
#include <cuda_bf16.h>
#include <math.h>
#include <stdint.h>

#define NN   50000
#define EE   800000
#define DD   128
#define LL   3
#define OUTD 40
#define SB   512
#define NSB  ((NN + SB - 1) / SB)   // 98
#define PADW 20
#define SZW  (128 * PADW)           // words per smem tile (2560)

// ---------------- scratch (device globals; no allocation allowed) ----------------
__device__ float    g_h[NN * DD];
__device__ float    g_xh[NN * DD];
__device__ float    g_xl[NN * DD];
__device__ float    g_xlocal[NN * DD];
__device__ float    g_as[2 * NN];   // double-buffered attention logit accumulators
__device__ float    g_ad[2 * NN];
__device__ int      g_deg[NN];
__device__ int      g_fill[NN];
__device__ int      g_rowptr[NN + 1];
__device__ int      g_esrc[EE];
__device__ int      g_src[EE];
__device__ int      g_dst[EE];
__device__ int      g_bsum[NSB];
__device__ int      g_boff[128];
// packed bf16 pairs (hi/lo) along k: [row][64 words]
__device__ uint32_t g_ah[NN * 64];
__device__ uint32_t g_al[NN * 64];
// pre-split weights: [wslot][n][64 words], 10 slots
__device__ uint32_t g_wsh[10 * 128 * 64];
__device__ uint32_t g_wsl[10 * 128 * 64];

__device__ __forceinline__ void bsplit(float v, uint32_t& h, uint32_t& l) {
    __nv_bfloat16 bh = __float2bfloat16_rn(v);
    float r = v - __bfloat162float(bh);
    __nv_bfloat16 bl = __float2bfloat16_rn(r);
    h = (uint32_t)__bfloat16_as_ushort(bh);
    l = (uint32_t)__bfloat16_as_ushort(bl);
}

__device__ __forceinline__ void cp16(void* dst_s, const void* src_g) {
    uint32_t d = (uint32_t)__cvta_generic_to_shared(dst_s);
    asm volatile("cp.async.cg.shared.global [%0], [%1], 16;" :: "r"(d), "l"(src_g));
}

// ---------------- edge decode + degree histogram (fused) ----------------
__global__ void decode_deg_k(const int* __restrict__ ei32) {
    bool is64 = (ei32[1] == 0 && ei32[3] == 0 && ei32[5] == 0 && ei32[7] == 0);
    int e = blockIdx.x * blockDim.x + threadIdx.x;
    if (e < EE) {
        int s, d;
        if (is64) {
            s = ei32[2 * (size_t)e];
            d = ei32[2 * ((size_t)EE + e)];
        } else {
            s = ei32[e];
            d = ei32[EE + e];
        }
        g_src[e] = s;
        g_dst[e] = d;
        atomicAdd(&g_deg[d], 1);
    }
}

__global__ void zero_k() {
    int i = blockIdx.x * blockDim.x + threadIdx.x;
    if (i < NN) {
        g_deg[i] = 0; g_fill[i] = 0;
        g_as[i] = 0.f; g_ad[i] = 0.f;
        g_as[NN + i] = 0.f; g_ad[NN + i] = 0.f;
    }
}

__global__ void pscan_k() {
    __shared__ int sh[SB];
    int t = threadIdx.x;
    int i = blockIdx.x * SB + t;
    int v = (i < NN) ? g_deg[i] : 0;
    sh[t] = v;
    __syncthreads();
    for (int o = 1; o < SB; o <<= 1) {
        int a = (t >= o) ? sh[t - o] : 0;
        __syncthreads();
        sh[t] += a;
        __syncthreads();
    }
    if (i < NN) g_rowptr[i] = sh[t] - v;
    if (t == SB - 1) g_bsum[blockIdx.x] = sh[t];
}

__global__ void bscan_k() {
    __shared__ int sh[128];
    int t = threadIdx.x;
    int v = (t < NSB) ? g_bsum[t] : 0;
    sh[t] = v;
    __syncthreads();
    for (int o = 1; o < 128; o <<= 1) {
        int a = (t >= o) ? sh[t - o] : 0;
        __syncthreads();
        sh[t] += a;
        __syncthreads();
    }
    g_boff[t] = sh[t] - v;
}

__global__ void addoff_k() {
    int i = blockIdx.x * blockDim.x + threadIdx.x;
    if (i < NN) g_rowptr[i] += g_boff[i / SB];
    if (i == 0) g_rowptr[NN] = EE;
}

__global__ void scat_k() {
    int e = blockIdx.x * blockDim.x + threadIdx.x;
    if (e < EE) {
        int d = g_dst[e];
        int p = g_rowptr[d] + atomicAdd(&g_fill[d], 1);
        g_esrc[p] = g_src[e];
    }
}

// ---------------- one-time weight split ----------------
__global__ void split_w_k(const float* __restrict__ W_in, const float* __restrict__ W_h,
                          const float* __restrict__ W_gat, const float* __restrict__ W_l) {
    int idx = blockIdx.x * blockDim.x + threadIdx.x;   // 10*64*128
    if (idx >= 10 * 64 * 128) return;
    int w   = idx >> 13;
    int kw  = (idx >> 7) & 63;
    int n   = idx & 127;
    const float* base;
    if (w == 0) base = W_in;
    else {
        int layer = (w - 1) / 3, t = (w - 1) % 3;
        base = (t == 0 ? W_h : t == 1 ? W_gat : W_l) + (size_t)layer * DD * DD;
    }
    float v0 = base[(size_t)(2 * kw) * DD + n];
    float v1 = base[(size_t)(2 * kw + 1) * DD + n];
    uint32_t h0, l0, h1, l1;
    bsplit(v0, h0, l0); bsplit(v1, h1, l1);
    g_wsh[(size_t)w * 8192 + n * 64 + kw] = h0 | (h1 << 16);
    g_wsl[(size_t)w * 8192 + n * 64 + kw] = l0 | (l1 << 16);
}

// ---------------- bf16x3 GEMM, cp.async double-buffered, fused attn logits ----------------
// FP32A=true: A operand is fp32 (split during staging) — used for lin_in.
struct GemmArgs2 {
    int          wslot[3];
    const float* bias[3];
    float*       out[3];
    int          epi[3];     // 0 none, 1 bias, 2 bias+relu
    int          emit_split;
    int          attn_w;     // which w computes attention logits (-1 = none)
    int          attn_slot;  // accumulator slot (0/1)
    const float* attn_a;
    const float* attn_d;
};

extern __shared__ uint32_t smem_dyn[];

template <bool FP32A>
__global__ __launch_bounds__(256, 2)
void mma_gemm_k(const uint32_t* __restrict__ Ah, const uint32_t* __restrict__ Al,
                const float* __restrict__ A32, GemmArgs2 args) {
    const int tid  = threadIdx.x;
    const int lane = tid & 31;
    const int wid  = tid >> 5;
    const int wm   = (wid >> 1) * 32;
    const int wn   = (wid & 1) * 64;
    const int row0 = blockIdx.x * 128;
    const int w    = blockIdx.y;

    const uint32_t* Wh = g_wsh + (size_t)args.wslot[w] * 8192;
    const uint32_t* Wl = g_wsl + (size_t)args.wslot[w] * 8192;

    const int ar = lane >> 2;
    const int ac = lane & 3;

    float acc[2][8][4];
#pragma unroll
    for (int i = 0; i < 2; i++)
#pragma unroll
        for (int j = 0; j < 8; j++)
#pragma unroll
            for (int c = 0; c < 4; c++) acc[i][j][c] = 0.f;

    auto stage = [&](int kc, int s) {
        uint32_t* bAh = smem_dyn + s * 4 * SZW;
        uint32_t* bAl = bAh + SZW;
        uint32_t* bWh = bAl + SZW;
        uint32_t* bWl = bWh + SZW;
        const int kwc = kc >> 1;
#pragma unroll
        for (int t = tid; t < 512; t += 256) {
            int m = t >> 2, q = t & 3;
            int row = row0 + m;
            uint32_t* dh = &bAh[m * PADW + 4 * q];
            uint32_t* dl = &bAl[m * PADW + 4 * q];
            if (FP32A) {
                uint4 h4 = make_uint4(0, 0, 0, 0), l4 = make_uint4(0, 0, 0, 0);
                if (row < NN) {
                    const float4* xr = (const float4*)(A32 + (size_t)row * DD + kc + 8 * q);
                    float4 v0 = xr[0], v1 = xr[1];
                    uint32_t h0, l0, h1, l1;
                    bsplit(v0.x, h0, l0); bsplit(v0.y, h1, l1);
                    h4.x = h0 | (h1 << 16); l4.x = l0 | (l1 << 16);
                    bsplit(v0.z, h0, l0); bsplit(v0.w, h1, l1);
                    h4.y = h0 | (h1 << 16); l4.y = l0 | (l1 << 16);
                    bsplit(v1.x, h0, l0); bsplit(v1.y, h1, l1);
                    h4.z = h0 | (h1 << 16); l4.z = l0 | (l1 << 16);
                    bsplit(v1.z, h0, l0); bsplit(v1.w, h1, l1);
                    h4.w = h0 | (h1 << 16); l4.w = l0 | (l1 << 16);
                }
                *(uint4*)dh = h4;
                *(uint4*)dl = l4;
            } else {
                if (row < NN) {
                    size_t o = (size_t)row * 64 + kwc + 4 * q;
                    cp16(dh, &Ah[o]);
                    cp16(dl, &Al[o]);
                } else {
                    *(uint4*)dh = make_uint4(0, 0, 0, 0);
                    *(uint4*)dl = make_uint4(0, 0, 0, 0);
                }
            }
        }
#pragma unroll
        for (int t = tid; t < 512; t += 256) {
            int n = t >> 2, q = t & 3;
            size_t o = (size_t)n * 64 + kwc + 4 * q;
            cp16(&bWh[n * PADW + 4 * q], &Wh[o]);
            cp16(&bWl[n * PADW + 4 * q], &Wl[o]);
        }
        asm volatile("cp.async.commit_group;");
    };

    stage(0, 0);

#pragma unroll
    for (int c = 0; c < 4; c++) {
        if (c < 3) stage((c + 1) * 32, (c + 1) & 1);
        if (c < 3) asm volatile("cp.async.wait_group 1;");
        else       asm volatile("cp.async.wait_group 0;");
        __syncthreads();

        const uint32_t* bAh = smem_dyn + (c & 1) * 4 * SZW;
        const uint32_t* bAl = bAh + SZW;
        const uint32_t* bWh = bAl + SZW;
        const uint32_t* bWl = bWh + SZW;

#pragma unroll
        for (int s = 0; s < 2; s++) {
            const int kb = s * 8;
            uint32_t ah[2][4], al[2][4];
#pragma unroll
            for (int i = 0; i < 2; i++) {
                int m = wm + i * 16 + ar;
                ah[i][0] = bAh[m * PADW + kb + ac];
                ah[i][1] = bAh[(m + 8) * PADW + kb + ac];
                ah[i][2] = bAh[m * PADW + kb + ac + 4];
                ah[i][3] = bAh[(m + 8) * PADW + kb + ac + 4];
                al[i][0] = bAl[m * PADW + kb + ac];
                al[i][1] = bAl[(m + 8) * PADW + kb + ac];
                al[i][2] = bAl[m * PADW + kb + ac + 4];
                al[i][3] = bAl[(m + 8) * PADW + kb + ac + 4];
            }
#pragma unroll
            for (int j = 0; j < 8; j++) {
                int n = wn + j * 8 + ar;
                uint32_t bh0 = bWh[n * PADW + kb + ac];
                uint32_t bh1 = bWh[n * PADW + kb + ac + 4];
                uint32_t bl0 = bWl[n * PADW + kb + ac];
                uint32_t bl1 = bWl[n * PADW + kb + ac + 4];
#pragma unroll
                for (int i = 0; i < 2; i++) {
                    asm volatile(
                        "mma.sync.aligned.m16n8k16.row.col.f32.bf16.bf16.f32 "
                        "{%0,%1,%2,%3}, {%4,%5,%6,%7}, {%8,%9}, {%0,%1,%2,%3};"
                        : "+f"(acc[i][j][0]), "+f"(acc[i][j][1]),
                          "+f"(acc[i][j][2]), "+f"(acc[i][j][3])
                        : "r"(ah[i][0]), "r"(ah[i][1]), "r"(ah[i][2]), "r"(ah[i][3]),
                          "r"(bh0), "r"(bh1));
                    asm volatile(
                        "mma.sync.aligned.m16n8k16.row.col.f32.bf16.bf16.f32 "
                        "{%0,%1,%2,%3}, {%4,%5,%6,%7}, {%8,%9}, {%0,%1,%2,%3};"
                        : "+f"(acc[i][j][0]), "+f"(acc[i][j][1]),
                          "+f"(acc[i][j][2]), "+f"(acc[i][j][3])
                        : "r"(ah[i][0]), "r"(ah[i][1]), "r"(ah[i][2]), "r"(ah[i][3]),
                          "r"(bl0), "r"(bl1));
                    asm volatile(
                        "mma.sync.aligned.m16n8k16.row.col.f32.bf16.bf16.f32 "
                        "{%0,%1,%2,%3}, {%4,%5,%6,%7}, {%8,%9}, {%0,%1,%2,%3};"
                        : "+f"(acc[i][j][0]), "+f"(acc[i][j][1]),
                          "+f"(acc[i][j][2]), "+f"(acc[i][j][3])
                        : "r"(al[i][0]), "r"(al[i][1]), "r"(al[i][2]), "r"(al[i][3]),
                          "r"(bh0), "r"(bh1));
                }
            }
        }
        __syncthreads();
    }

    // ---- epilogue ----
    const int epi = args.epi[w];
    const float* bias = args.bias[w];
    float* out = args.out[w];
    const int emit = args.emit_split;
    const bool do_attn = (w == args.attn_w);
    float* asb = g_as + (size_t)args.attn_slot * NN;
    float* adb = g_ad + (size_t)args.attn_slot * NN;
    float ps[2] = {0.f, 0.f}, pd[2] = {0.f, 0.f};
    float ps2[2] = {0.f, 0.f}, pd2[2] = {0.f, 0.f};

#pragma unroll
    for (int i = 0; i < 2; i++) {
#pragma unroll
        for (int j = 0; j < 8; j++) {
            int cc = wn + j * 8 + ac * 2;
            float bx = 0.f, by = 0.f;
            if (epi >= 1) { bx = bias[cc]; by = bias[cc + 1]; }
            float c0 = acc[i][j][0] + bx, c1 = acc[i][j][1] + by;
            float c2 = acc[i][j][2] + bx, c3 = acc[i][j][3] + by;
            if (epi == 2) {
                c0 = fmaxf(c0, 0.f); c1 = fmaxf(c1, 0.f);
                c2 = fmaxf(c2, 0.f); c3 = fmaxf(c3, 0.f);
            }
            if (do_attn) {
                float a0 = args.attn_a[cc], a1 = args.attn_a[cc + 1];
                float d0 = args.attn_d[cc], d1 = args.attn_d[cc + 1];
                ps[i]  += c0 * a0 + c1 * a1;
                pd[i]  += c0 * d0 + c1 * d1;
                ps2[i] += c2 * a0 + c3 * a1;
                pd2[i] += c2 * d0 + c3 * d1;
            }
            int r0 = row0 + wm + i * 16 + ar;
            if (out) {
                if (r0 < NN)     *(float2*)&out[(size_t)r0 * DD + cc]       = make_float2(c0, c1);
                if (r0 + 8 < NN) *(float2*)&out[(size_t)(r0 + 8) * DD + cc] = make_float2(c2, c3);
            }
            if (emit) {
                uint32_t h0, l0, h1, l1;
                if (r0 < NN) {
                    bsplit(c0, h0, l0); bsplit(c1, h1, l1);
                    g_ah[(size_t)r0 * 64 + (cc >> 1)] = h0 | (h1 << 16);
                    g_al[(size_t)r0 * 64 + (cc >> 1)] = l0 | (l1 << 16);
                }
                if (r0 + 8 < NN) {
                    bsplit(c2, h0, l0); bsplit(c3, h1, l1);
                    g_ah[(size_t)(r0 + 8) * 64 + (cc >> 1)] = h0 | (h1 << 16);
                    g_al[(size_t)(r0 + 8) * 64 + (cc >> 1)] = l0 | (l1 << 16);
                }
            }
        }
    }

    if (do_attn) {
#pragma unroll
        for (int i = 0; i < 2; i++) {
#pragma unroll
            for (int o = 1; o <= 2; o <<= 1) {
                ps[i]  += __shfl_xor_sync(0xFFFFFFFFu, ps[i],  o);
                pd[i]  += __shfl_xor_sync(0xFFFFFFFFu, pd[i],  o);
                ps2[i] += __shfl_xor_sync(0xFFFFFFFFu, ps2[i], o);
                pd2[i] += __shfl_xor_sync(0xFFFFFFFFu, pd2[i], o);
            }
            if (ac == 0) {
                int r0 = row0 + wm + i * 16 + ar;
                if (r0 < NN) {
                    atomicAdd(&asb[r0], ps[i]);
                    atomicAdd(&adb[r0], pd[i]);
                }
                if (r0 + 8 < NN) {
                    atomicAdd(&asb[r0 + 8], ps2[i]);
                    atomicAdd(&adb[r0 + 8], pd2[i]);
                }
            }
        }
    }
}

// ---------------- small FFMA GEMM for the prediction head (NCOL=40) ----------------
template <int NCOL>
__global__ void gemm_small_k(const float* __restrict__ A, const float* __restrict__ W,
                             const float* __restrict__ bias, float* __restrict__ C) {
    constexpr int ROWS = 32;
    constexpr int KT   = 32;
    __shared__ float sA[ROWS][DD];
    __shared__ float sW[KT][NCOL];
    int tid  = threadIdx.x;
    int row0 = blockIdx.x * ROWS;

    {
        const float4* Af  = (const float4*)A;
        float4*       sAf = (float4*)sA;
#pragma unroll
        for (int i = 0; i < 4; i++) {
            int idx = tid + i * 256;
            int r = idx >> 5, c = idx & 31;
            float4 v = make_float4(0.f, 0.f, 0.f, 0.f);
            if (row0 + r < NN) v = Af[(size_t)(row0 + r) * 32 + c];
            sAf[idx] = v;
        }
    }

    int tx = tid & 31, ty = tid >> 5;
    const int col = tx * 4;
    float acc[4][4];
#pragma unroll
    for (int i = 0; i < 4; i++)
#pragma unroll
        for (int j = 0; j < 4; j++) acc[i][j] = 0.f;

    for (int kt = 0; kt < DD; kt += KT) {
        __syncthreads();
        {
            const float4* Wf  = (const float4*)(W + kt * NCOL);
            float4*       sWf = (float4*)sW;
            constexpr int T4 = KT * NCOL / 4;
            for (int i = tid; i < T4; i += 256) sWf[i] = Wf[i];
        }
        __syncthreads();
#pragma unroll
        for (int k = 0; k < KT; k++) {
            float4 wv = make_float4(0.f, 0.f, 0.f, 0.f);
            if (col < NCOL) wv = *(const float4*)&sW[k][col];
#pragma unroll
            for (int i = 0; i < 4; i++) {
                float a = sA[ty + i * 8][kt + k];
                acc[i][0] += a * wv.x;
                acc[i][1] += a * wv.y;
                acc[i][2] += a * wv.z;
                acc[i][3] += a * wv.w;
            }
        }
    }

    if (col < NCOL) {
        float4 bv = *(const float4*)&bias[col];
#pragma unroll
        for (int i = 0; i < 4; i++) {
            int row = row0 + ty + i * 8;
            if (row < NN) {
                float4 o;
                o.x = acc[i][0] + bv.x;
                o.y = acc[i][1] + bv.y;
                o.z = acc[i][2] + bv.z;
                o.w = acc[i][3] + bv.w;
                *(float4*)&C[(size_t)row * NCOL + col] = o;
            }
        }
    }
}

// ---------------- fused GAT aggregate + pointwise + emit split ----------------
// warp per destination node; edges register-cached (up to 4/lane = deg 128);
// rare longer rows recompute logits from L2-resident g_as.
__global__ void aggfuse_k(const float* __restrict__ xh,
                          const float* __restrict__ xlbuf, const float* __restrict__ hbuf,
                          const float* __restrict__ lng, const float* __restrict__ lnb,
                          const float* __restrict__ betas, int first, int slot) {
    int n    = (blockIdx.x * blockDim.x + threadIdx.x) >> 5;
    int lane = threadIdx.x & 31;
    if (n >= NN) return;
    const float* asb = g_as + (size_t)slot * NN;
    const float* adb = g_ad + (size_t)slot * NN;
    int s0 = g_rowptr[n], s1 = g_rowptr[n + 1];
    float adn = adb[n];

    // pass 1: online softmax; cache up to 4 (src, logit) pairs per lane
    int   sc[4];
    float ec[4];
    float m = -1e30f, d = 0.f;
    {
        int k = 0;
        for (int i = s0 + lane; i < s1; i += 32, k++) {
            int s  = g_esrc[i];
            float e = asb[s] + adn;
            e = e > 0.f ? e : 0.2f * e;
            if (k < 4) { sc[k] = s; ec[k] = e; }
            if (e > m) { d = d * __expf(m - e) + 1.f; m = e; }
            else       { d += __expf(e - m); }
        }
    }
#pragma unroll
    for (int o = 16; o; o >>= 1) {
        float mo = __shfl_xor_sync(0xFFFFFFFFu, m, o);
        float do_ = __shfl_xor_sync(0xFFFFFFFFu, d, o);
        if (mo > m) { d = d * __expf(m - mo) + do_; m = mo; }
        else        { d += do_ * __expf(mo - m); }
    }
    float inv = 1.f / (d + 1e-16f);

    // pass 2: weighted gather (weights from register cache; fallback recompute)
    float4 ag = make_float4(0.f, 0.f, 0.f, 0.f);
    {
        int k = 0;
        for (int base = s0; base < s1; base += 32, k++) {
            int idx = base + lane;
            float w = 0.f;
            int   s = 0;
            if (idx < s1) {
                float e;
                if (k < 4) { s = sc[k]; e = ec[k]; }
                else {
                    s = g_esrc[idx];
                    e = asb[s] + adn;
                    e = e > 0.f ? e : 0.2f * e;
                }
                w = __expf(e - m) * inv;
            }
            int cnt = min(32, s1 - base);
            for (int j = 0; j < cnt; j++) {
                float wj = __shfl_sync(0xFFFFFFFFu, w, j);
                int   sj = __shfl_sync(0xFFFFFFFFu, s, j);
                float4 v = ((const float4*)(xh + (size_t)sj * DD))[lane];
                ag.x += wj * v.x; ag.y += wj * v.y;
                ag.z += wj * v.z; ag.w += wj * v.w;
            }
        }
    }

    // ---- pointwise (agg stays in registers) ----
    size_t off = (size_t)n * DD;
    float4 xl = ((const float4*)(xlbuf + off))[lane];
    float4 xn;
    xn.x = fmaxf(ag.x + xl.x, 0.f);
    xn.y = fmaxf(ag.y + xl.y, 0.f);
    xn.z = fmaxf(ag.z + xl.z, 0.f);
    xn.w = fmaxf(ag.w + xl.w, 0.f);

    float4 hh = ((const float4*)(hbuf + off))[lane];
    float4 t;
    t.x = hh.x * xn.x; t.y = hh.y * xn.y; t.z = hh.z * xn.z; t.w = hh.w * xn.w;

    float sum = t.x + t.y + t.z + t.w;
#pragma unroll
    for (int o = 16; o; o >>= 1) sum += __shfl_xor_sync(0xFFFFFFFFu, sum, o);
    float mu = sum * (1.f / 128.f);

    float4 dc;
    dc.x = t.x - mu; dc.y = t.y - mu; dc.z = t.z - mu; dc.w = t.w - mu;
    float ss = dc.x * dc.x + dc.y * dc.y + dc.z * dc.z + dc.w * dc.w;
#pragma unroll
    for (int o = 16; o; o >>= 1) ss += __shfl_xor_sync(0xFFFFFFFFu, ss, o);
    float rs = rsqrtf(ss * (1.f / 128.f) + 1e-5f);

    float4 g  = ((const float4*)lng)[lane];
    float4 b  = ((const float4*)lnb)[lane];
    float4 be = ((const float4*)betas)[lane];
    be.x = 1.f / (1.f + __expf(-be.x));
    be.y = 1.f / (1.f + __expf(-be.y));
    be.z = 1.f / (1.f + __expf(-be.z));
    be.w = 1.f / (1.f + __expf(-be.w));

    float4 y;
    y.x = dc.x * rs * g.x + b.x;
    y.y = dc.y * rs * g.y + b.y;
    y.z = dc.z * rs * g.z + b.z;
    y.w = dc.w * rs * g.w + b.w;

    float4 xo;
    xo.x = (1.f - be.x) * y.x + be.x * xn.x;
    xo.y = (1.f - be.y) * y.y + be.y * xn.y;
    xo.z = (1.f - be.z) * y.z + be.z * xn.z;
    xo.w = (1.f - be.w) * y.w + be.w * xn.w;

    // emit bf16 split of new x
    {
        uint32_t hx, lx, hy, ly, hz, lz, hw, lw;
        bsplit(xo.x, hx, lx); bsplit(xo.y, hy, ly);
        bsplit(xo.z, hz, lz); bsplit(xo.w, hw, lw);
        size_t o2 = (size_t)n * 64 + 2 * lane;
        g_ah[o2]     = hx | (hy << 16);
        g_ah[o2 + 1] = hz | (hw << 16);
        g_al[o2]     = lx | (ly << 16);
        g_al[o2 + 1] = lz | (lw << 16);
    }

    if (first) {
        ((float4*)(g_xlocal + off))[lane] = xo;
    } else {
        float4 p = ((const float4*)(g_xlocal + off))[lane];
        p.x += xo.x; p.y += xo.y; p.z += xo.z; p.w += xo.w;
        ((float4*)(g_xlocal + off))[lane] = p;
    }

    // zero the OTHER attention slot (used by the next layer's GEMM)
    if (lane == 0) {
        int os = slot ^ 1;
        g_as[(size_t)os * NN + n] = 0.f;
        g_ad[(size_t)os * NN + n] = 0.f;
    }
}

// ---------------- host ----------------
extern "C" void kernel_launch(void* const* d_in, const int* in_sizes, int n_in,
                              void* d_out, int out_size) {
    const float* x       = (const float*)d_in[0];
    const int*   ei32    = (const int*)d_in[1];
    const float* W_in    = (const float*)d_in[2];
    const float* b_in    = (const float*)d_in[3];
    const float* W_h     = (const float*)d_in[4];
    const float* b_h     = (const float*)d_in[5];
    const float* W_gat   = (const float*)d_in[6];
    const float* att_src = (const float*)d_in[7];
    const float* att_dst = (const float*)d_in[8];
    const float* W_l     = (const float*)d_in[9];
    const float* b_l     = (const float*)d_in[10];
    const float* ln_g    = (const float*)d_in[11];
    const float* ln_b    = (const float*)d_in[12];
    const float* betas   = (const float*)d_in[13];
    const float* W_pred  = (const float*)d_in[14];
    const float* b_pred  = (const float*)d_in[15];
    float*       out     = (float*)d_out;

    float *ph, *pxh, *pxl, *pxloc;
    uint32_t *pah, *pal;
    cudaGetSymbolAddress((void**)&ph,    g_h);
    cudaGetSymbolAddress((void**)&pxh,   g_xh);
    cudaGetSymbolAddress((void**)&pxl,   g_xl);
    cudaGetSymbolAddress((void**)&pxloc, g_xlocal);
    cudaGetSymbolAddress((void**)&pah,   g_ah);
    cudaGetSymbolAddress((void**)&pal,   g_al);

    const int dynsmem = 2 * 4 * SZW * 4;   // 81920 bytes
    static cudaStream_t s_side = nullptr;
    static cudaEvent_t  ev_fork = nullptr, ev_join = nullptr;
    if (!s_side) {
        cudaFuncSetAttribute(mma_gemm_k<false>, cudaFuncAttributeMaxDynamicSharedMemorySize, dynsmem);
        cudaFuncSetAttribute(mma_gemm_k<true>,  cudaFuncAttributeMaxDynamicSharedMemorySize, dynsmem);
        cudaStreamCreateWithFlags(&s_side, cudaStreamNonBlocking);
        cudaEventCreateWithFlags(&ev_fork, cudaEventDisableTiming);
        cudaEventCreateWithFlags(&ev_join, cudaEventDisableTiming);
    }

    dim3 gE((EE + 255) / 256);
    dim3 gN((NN + 255) / 256);
    dim3 gW((NN + 7) / 8);
    dim3 gG((NN + 31) / 32);
    dim3 gM((NN + 127) / 128, 1);
    dim3 gM3((NN + 127) / 128, 3);

    // zeroing on main (prereq for BOTH branches)
    zero_k<<<gN, 256>>>();

    // fork: CSR build on side stream
    cudaEventRecord(ev_fork, 0);
    cudaStreamWaitEvent(s_side, ev_fork, 0);
    decode_deg_k<<<gE, 256, 0, s_side>>>(ei32);
    pscan_k<<<NSB, SB, 0, s_side>>>();
    bscan_k<<<1, 128, 0, s_side>>>();
    addoff_k<<<gN, 256, 0, s_side>>>();
    scat_k<<<gE, 256, 0, s_side>>>();
    cudaEventRecord(ev_join, s_side);

    // main: weight split + dense prologue (independent of CSR)
    split_w_k<<<(10 * 64 * 128 + 255) / 256, 256>>>(W_in, W_h, W_gat, W_l);

    // input projection: x @ W_in + b_in -> split only (A staged from fp32 x)
    {
        GemmArgs2 a{};
        a.wslot[0] = 0; a.bias[0] = b_in; a.out[0] = nullptr; a.epi[0] = 1;
        a.emit_split = 1; a.attn_w = -1;
        mma_gemm_k<true><<<gM, 256, dynsmem>>>(nullptr, nullptr, x, a);
    }

    // layer 0 GEMM is also CSR-independent
    {
        GemmArgs2 a{};
        a.wslot[0] = 1; a.bias[0] = b_h; a.out[0] = ph;  a.epi[0] = 2;
        a.wslot[1] = 2; a.bias[1] = nullptr; a.out[1] = pxh; a.epi[1] = 0;
        a.wslot[2] = 3; a.bias[2] = b_l; a.out[2] = pxl; a.epi[2] = 1;
        a.emit_split = 0;
        a.attn_w = 1; a.attn_slot = 0;
        a.attn_a = att_src; a.attn_d = att_dst;
        mma_gemm_k<false><<<gM3, 256, dynsmem>>>(pah, pal, nullptr, a);
    }

    // join: aggfuse needs the CSR
    cudaStreamWaitEvent(0, ev_join, 0);

    for (int i = 0; i < LL; i++) {
        if (i > 0) {
            GemmArgs2 a{};
            a.wslot[0] = 1 + 3 * i;     a.bias[0] = b_h + i * DD; a.out[0] = ph;  a.epi[0] = 2;
            a.wslot[1] = 1 + 3 * i + 1; a.bias[1] = nullptr;      a.out[1] = pxh; a.epi[1] = 0;
            a.wslot[2] = 1 + 3 * i + 2; a.bias[2] = b_l + i * DD; a.out[2] = pxl; a.epi[2] = 1;
            a.emit_split = 0;
            a.attn_w = 1; a.attn_slot = i & 1;
            a.attn_a = att_src + i * DD; a.attn_d = att_dst + i * DD;
            mma_gemm_k<false><<<gM3, 256, dynsmem>>>(pah, pal, nullptr, a);
        }

        aggfuse_k<<<gW, 256>>>(pxh, pxl, ph,
                               ln_g + i * DD, ln_b + i * DD, betas + i * DD,
                               i == 0, i & 1);
    }

    gemm_small_k<OUTD><<<gG, 256>>>(pxloc, W_pred, b_pred, out);
}

// round 14
// speedup vs baseline: 1.0125x; 1.0125x over previous
#include <cuda_runtime.h>
#include <cuda_bf16.h>
#include <math.h>
#include <stdint.h>

#define NN   50000
#define EE   800000
#define DD   128
#define LL   3
#define OUTD 40
#define SB   512
#define NSB  ((NN + SB - 1) / SB)   // 98
#define PADW 20
#define SZW  (128 * PADW)           // words per smem tile (2560)

// ---------------- scratch (device globals; no allocation allowed) ----------------
__device__ float    g_h[NN * DD];
__device__ float    g_xh[NN * DD];
__device__ float    g_xl[NN * DD];
__device__ float    g_xlocal[NN * DD];
__device__ float    g_as[2 * NN];   // double-buffered attention logit accumulators
__device__ float    g_ad[2 * NN];
__device__ int      g_deg[NN];
__device__ int      g_fill[NN];
__device__ int      g_rowptr[NN + 1];
__device__ int      g_esrc[EE];
__device__ int      g_src[EE];
__device__ int      g_dst[EE];
__device__ int      g_bsum[NSB];
__device__ int      g_boff[128];
// packed bf16 pairs (hi/lo) along k: [row][64 words]
__device__ uint32_t g_inh[NN * 64];
__device__ uint32_t g_inl[NN * 64];
__device__ uint32_t g_ah[NN * 64];
__device__ uint32_t g_al[NN * 64];
// pre-split weights: [wslot][n][64 words], 10 slots
__device__ uint32_t g_wsh[10 * 128 * 64];
__device__ uint32_t g_wsl[10 * 128 * 64];

__device__ __forceinline__ void bsplit(float v, uint32_t& h, uint32_t& l) {
    __nv_bfloat16 bh = __float2bfloat16_rn(v);
    float r = v - __bfloat162float(bh);
    __nv_bfloat16 bl = __float2bfloat16_rn(r);
    h = (uint32_t)__bfloat16_as_ushort(bh);
    l = (uint32_t)__bfloat16_as_ushort(bl);
}

__device__ __forceinline__ void cp16(void* dst_s, const void* src_g) {
    uint32_t d = (uint32_t)__cvta_generic_to_shared(dst_s);
    asm volatile("cp.async.cg.shared.global [%0], [%1], 16;" :: "r"(d), "l"(src_g));
}

// ---------------- edge decode + degree histogram (fused) ----------------
__global__ void decode_deg_k(const int* __restrict__ ei32) {
    bool is64 = (ei32[1] == 0 && ei32[3] == 0 && ei32[5] == 0 && ei32[7] == 0);
    int e = blockIdx.x * blockDim.x + threadIdx.x;
    if (e < EE) {
        int s, d;
        if (is64) {
            s = ei32[2 * (size_t)e];
            d = ei32[2 * ((size_t)EE + e)];
        } else {
            s = ei32[e];
            d = ei32[EE + e];
        }
        g_src[e] = s;
        g_dst[e] = d;
        atomicAdd(&g_deg[d], 1);
    }
}

__global__ void zero_k() {
    int i = blockIdx.x * blockDim.x + threadIdx.x;
    if (i < NN) {
        g_deg[i] = 0; g_fill[i] = 0;
        g_as[i] = 0.f; g_ad[i] = 0.f;
        g_as[NN + i] = 0.f; g_ad[NN + i] = 0.f;
    }
}

__global__ void pscan_k() {
    __shared__ int sh[SB];
    int t = threadIdx.x;
    int i = blockIdx.x * SB + t;
    int v = (i < NN) ? g_deg[i] : 0;
    sh[t] = v;
    __syncthreads();
    for (int o = 1; o < SB; o <<= 1) {
        int a = (t >= o) ? sh[t - o] : 0;
        __syncthreads();
        sh[t] += a;
        __syncthreads();
    }
    if (i < NN) g_rowptr[i] = sh[t] - v;
    if (t == SB - 1) g_bsum[blockIdx.x] = sh[t];
}

__global__ void bscan_k() {
    __shared__ int sh[128];
    int t = threadIdx.x;
    int v = (t < NSB) ? g_bsum[t] : 0;
    sh[t] = v;
    __syncthreads();
    for (int o = 1; o < 128; o <<= 1) {
        int a = (t >= o) ? sh[t - o] : 0;
        __syncthreads();
        sh[t] += a;
        __syncthreads();
    }
    g_boff[t] = sh[t] - v;
}

__global__ void addoff_k() {
    int i = blockIdx.x * blockDim.x + threadIdx.x;
    if (i < NN) g_rowptr[i] += g_boff[i / SB];
    if (i == 0) g_rowptr[NN] = EE;
}

__global__ void scat_k() {
    int e = blockIdx.x * blockDim.x + threadIdx.x;
    if (e < EE) {
        int d = g_dst[e];
        int p = g_rowptr[d] + atomicAdd(&g_fill[d], 1);
        g_esrc[p] = g_src[e];
    }
}

// ---------------- one-time weight split ----------------
__global__ void split_w_k(const float* __restrict__ W_in, const float* __restrict__ W_h,
                          const float* __restrict__ W_gat, const float* __restrict__ W_l) {
    int idx = blockIdx.x * blockDim.x + threadIdx.x;   // 10*64*128
    if (idx >= 10 * 64 * 128) return;
    int w   = idx >> 13;
    int kw  = (idx >> 7) & 63;
    int n   = idx & 127;
    const float* base;
    if (w == 0) base = W_in;
    else {
        int layer = (w - 1) / 3, t = (w - 1) % 3;
        base = (t == 0 ? W_h : t == 1 ? W_gat : W_l) + (size_t)layer * DD * DD;
    }
    float v0 = base[(size_t)(2 * kw) * DD + n];
    float v1 = base[(size_t)(2 * kw + 1) * DD + n];
    uint32_t h0, l0, h1, l1;
    bsplit(v0, h0, l0); bsplit(v1, h1, l1);
    g_wsh[(size_t)w * 8192 + n * 64 + kw] = h0 | (h1 << 16);
    g_wsl[(size_t)w * 8192 + n * 64 + kw] = l0 | (l1 << 16);
}

// ---------------- one-time input split ----------------
__global__ void split_x_k(const float* __restrict__ x) {
    int t = blockIdx.x * blockDim.x + threadIdx.x;     // NN*32
    if (t >= NN * 32) return;
    int row = t >> 5, q = t & 31;
    float4 v = ((const float4*)x)[(size_t)row * 32 + q];
    uint32_t hx, lx, hy, ly, hz, lz, hw, lw;
    bsplit(v.x, hx, lx); bsplit(v.y, hy, ly);
    bsplit(v.z, hz, lz); bsplit(v.w, hw, lw);
    size_t o = (size_t)row * 64 + 2 * q;
    g_inh[o]     = hx | (hy << 16);
    g_inh[o + 1] = hz | (hw << 16);
    g_inl[o]     = lx | (ly << 16);
    g_inl[o + 1] = lz | (lw << 16);
}

// ---------------- bf16x3 GEMM, cp.async double-buffered, fused attn logits ----------------
struct GemmArgs2 {
    int          wslot[3];
    const float* bias[3];
    float*       out[3];
    int          epi[3];     // 0 none, 1 bias, 2 bias+relu
    int          emit_split;
    int          attn_w;     // which w computes attention logits (-1 = none)
    int          attn_slot;  // accumulator slot (0/1)
    const float* attn_a;
    const float* attn_d;
};

extern __shared__ uint32_t smem_dyn[];

__global__ __launch_bounds__(256, 2)
void mma_gemm_k(const uint32_t* __restrict__ Ah, const uint32_t* __restrict__ Al,
                GemmArgs2 args) {
    const int tid  = threadIdx.x;
    const int lane = tid & 31;
    const int wid  = tid >> 5;
    const int wm   = (wid >> 1) * 32;
    const int wn   = (wid & 1) * 64;
    const int row0 = blockIdx.x * 128;
    const int w    = blockIdx.y;

    const uint32_t* Wh = g_wsh + (size_t)args.wslot[w] * 8192;
    const uint32_t* Wl = g_wsl + (size_t)args.wslot[w] * 8192;

    const int ar = lane >> 2;
    const int ac = lane & 3;

    float acc[2][8][4];
#pragma unroll
    for (int i = 0; i < 2; i++)
#pragma unroll
        for (int j = 0; j < 8; j++)
#pragma unroll
            for (int c = 0; c < 4; c++) acc[i][j][c] = 0.f;

    auto stage = [&](int kc, int s) {
        uint32_t* bAh = smem_dyn + s * 4 * SZW;
        uint32_t* bAl = bAh + SZW;
        uint32_t* bWh = bAl + SZW;
        uint32_t* bWl = bWh + SZW;
        const int kwc = kc >> 1;
#pragma unroll
        for (int t = tid; t < 512; t += 256) {
            int m = t >> 2, q = t & 3;
            int row = row0 + m;
            uint32_t* dh = &bAh[m * PADW + 4 * q];
            uint32_t* dl = &bAl[m * PADW + 4 * q];
            if (row < NN) {
                size_t o = (size_t)row * 64 + kwc + 4 * q;
                cp16(dh, &Ah[o]);
                cp16(dl, &Al[o]);
            } else {
                *(uint4*)dh = make_uint4(0, 0, 0, 0);
                *(uint4*)dl = make_uint4(0, 0, 0, 0);
            }
        }
#pragma unroll
        for (int t = tid; t < 512; t += 256) {
            int n = t >> 2, q = t & 3;
            size_t o = (size_t)n * 64 + kwc + 4 * q;
            cp16(&bWh[n * PADW + 4 * q], &Wh[o]);
            cp16(&bWl[n * PADW + 4 * q], &Wl[o]);
        }
        asm volatile("cp.async.commit_group;");
    };

    stage(0, 0);

#pragma unroll
    for (int c = 0; c < 4; c++) {
        if (c < 3) stage((c + 1) * 32, (c + 1) & 1);
        if (c < 3) asm volatile("cp.async.wait_group 1;");
        else       asm volatile("cp.async.wait_group 0;");
        __syncthreads();

        const uint32_t* bAh = smem_dyn + (c & 1) * 4 * SZW;
        const uint32_t* bAl = bAh + SZW;
        const uint32_t* bWh = bAl + SZW;
        const uint32_t* bWl = bWh + SZW;

#pragma unroll
        for (int s = 0; s < 2; s++) {
            const int kb = s * 8;
            uint32_t ah[2][4], al[2][4];
#pragma unroll
            for (int i = 0; i < 2; i++) {
                int m = wm + i * 16 + ar;
                ah[i][0] = bAh[m * PADW + kb + ac];
                ah[i][1] = bAh[(m + 8) * PADW + kb + ac];
                ah[i][2] = bAh[m * PADW + kb + ac + 4];
                ah[i][3] = bAh[(m + 8) * PADW + kb + ac + 4];
                al[i][0] = bAl[m * PADW + kb + ac];
                al[i][1] = bAl[(m + 8) * PADW + kb + ac];
                al[i][2] = bAl[m * PADW + kb + ac + 4];
                al[i][3] = bAl[(m + 8) * PADW + kb + ac + 4];
            }
#pragma unroll
            for (int j = 0; j < 8; j++) {
                int n = wn + j * 8 + ar;
                uint32_t bh0 = bWh[n * PADW + kb + ac];
                uint32_t bh1 = bWh[n * PADW + kb + ac + 4];
                uint32_t bl0 = bWl[n * PADW + kb + ac];
                uint32_t bl1 = bWl[n * PADW + kb + ac + 4];
#pragma unroll
                for (int i = 0; i < 2; i++) {
                    asm volatile(
                        "mma.sync.aligned.m16n8k16.row.col.f32.bf16.bf16.f32 "
                        "{%0,%1,%2,%3}, {%4,%5,%6,%7}, {%8,%9}, {%0,%1,%2,%3};"
                        : "+f"(acc[i][j][0]), "+f"(acc[i][j][1]),
                          "+f"(acc[i][j][2]), "+f"(acc[i][j][3])
                        : "r"(ah[i][0]), "r"(ah[i][1]), "r"(ah[i][2]), "r"(ah[i][3]),
                          "r"(bh0), "r"(bh1));
                    asm volatile(
                        "mma.sync.aligned.m16n8k16.row.col.f32.bf16.bf16.f32 "
                        "{%0,%1,%2,%3}, {%4,%5,%6,%7}, {%8,%9}, {%0,%1,%2,%3};"
                        : "+f"(acc[i][j][0]), "+f"(acc[i][j][1]),
                          "+f"(acc[i][j][2]), "+f"(acc[i][j][3])
                        : "r"(ah[i][0]), "r"(ah[i][1]), "r"(ah[i][2]), "r"(ah[i][3]),
                          "r"(bl0), "r"(bl1));
                    asm volatile(
                        "mma.sync.aligned.m16n8k16.row.col.f32.bf16.bf16.f32 "
                        "{%0,%1,%2,%3}, {%4,%5,%6,%7}, {%8,%9}, {%0,%1,%2,%3};"
                        : "+f"(acc[i][j][0]), "+f"(acc[i][j][1]),
                          "+f"(acc[i][j][2]), "+f"(acc[i][j][3])
                        : "r"(al[i][0]), "r"(al[i][1]), "r"(al[i][2]), "r"(al[i][3]),
                          "r"(bh0), "r"(bh1));
                }
            }
        }
        __syncthreads();
    }

    // ---- epilogue ----
    const int epi = args.epi[w];
    const float* bias = args.bias[w];
    float* out = args.out[w];
    const int emit = args.emit_split;
    const bool do_attn = (w == args.attn_w);
    float* asb = g_as + (size_t)args.attn_slot * NN;
    float* adb = g_ad + (size_t)args.attn_slot * NN;
    float ps[2] = {0.f, 0.f}, pd[2] = {0.f, 0.f};
    float ps2[2] = {0.f, 0.f}, pd2[2] = {0.f, 0.f};

#pragma unroll
    for (int i = 0; i < 2; i++) {
#pragma unroll
        for (int j = 0; j < 8; j++) {
            int cc = wn + j * 8 + ac * 2;
            float bx = 0.f, by = 0.f;
            if (epi >= 1) { bx = bias[cc]; by = bias[cc + 1]; }
            float c0 = acc[i][j][0] + bx, c1 = acc[i][j][1] + by;
            float c2 = acc[i][j][2] + bx, c3 = acc[i][j][3] + by;
            if (epi == 2) {
                c0 = fmaxf(c0, 0.f); c1 = fmaxf(c1, 0.f);
                c2 = fmaxf(c2, 0.f); c3 = fmaxf(c3, 0.f);
            }
            if (do_attn) {
                float a0 = args.attn_a[cc], a1 = args.attn_a[cc + 1];
                float d0 = args.attn_d[cc], d1 = args.attn_d[cc + 1];
                ps[i]  += c0 * a0 + c1 * a1;
                pd[i]  += c0 * d0 + c1 * d1;
                ps2[i] += c2 * a0 + c3 * a1;
                pd2[i] += c2 * d0 + c3 * d1;
            }
            int r0 = row0 + wm + i * 16 + ar;
            if (out) {
                if (r0 < NN)     *(float2*)&out[(size_t)r0 * DD + cc]       = make_float2(c0, c1);
                if (r0 + 8 < NN) *(float2*)&out[(size_t)(r0 + 8) * DD + cc] = make_float2(c2, c3);
            }
            if (emit) {
                uint32_t h0, l0, h1, l1;
                if (r0 < NN) {
                    bsplit(c0, h0, l0); bsplit(c1, h1, l1);
                    g_ah[(size_t)r0 * 64 + (cc >> 1)] = h0 | (h1 << 16);
                    g_al[(size_t)r0 * 64 + (cc >> 1)] = l0 | (l1 << 16);
                }
                if (r0 + 8 < NN) {
                    bsplit(c2, h0, l0); bsplit(c3, h1, l1);
                    g_ah[(size_t)(r0 + 8) * 64 + (cc >> 1)] = h0 | (h1 << 16);
                    g_al[(size_t)(r0 + 8) * 64 + (cc >> 1)] = l0 | (l1 << 16);
                }
            }
        }
    }

    if (do_attn) {
#pragma unroll
        for (int i = 0; i < 2; i++) {
#pragma unroll
            for (int o = 1; o <= 2; o <<= 1) {
                ps[i]  += __shfl_xor_sync(0xFFFFFFFFu, ps[i],  o);
                pd[i]  += __shfl_xor_sync(0xFFFFFFFFu, pd[i],  o);
                ps2[i] += __shfl_xor_sync(0xFFFFFFFFu, ps2[i], o);
                pd2[i] += __shfl_xor_sync(0xFFFFFFFFu, pd2[i], o);
            }
            if (ac == 0) {
                int r0 = row0 + wm + i * 16 + ar;
                if (r0 < NN) {
                    atomicAdd(&asb[r0], ps[i]);
                    atomicAdd(&adb[r0], pd[i]);
                }
                if (r0 + 8 < NN) {
                    atomicAdd(&asb[r0 + 8], ps2[i]);
                    atomicAdd(&adb[r0 + 8], pd2[i]);
                }
            }
        }
    }
}

// ---------------- small FFMA GEMM for the prediction head (NCOL=40) ----------------
template <int NCOL>
__global__ void gemm_small_k(const float* __restrict__ A, const float* __restrict__ W,
                             const float* __restrict__ bias, float* __restrict__ C) {
    constexpr int ROWS = 32;
    constexpr int KT   = 32;
    __shared__ float sA[ROWS][DD];
    __shared__ float sW[KT][NCOL];
    int tid  = threadIdx.x;
    int row0 = blockIdx.x * ROWS;

    {
        const float4* Af  = (const float4*)A;
        float4*       sAf = (float4*)sA;
#pragma unroll
        for (int i = 0; i < 4; i++) {
            int idx = tid + i * 256;
            int r = idx >> 5, c = idx & 31;
            float4 v = make_float4(0.f, 0.f, 0.f, 0.f);
            if (row0 + r < NN) v = Af[(size_t)(row0 + r) * 32 + c];
            sAf[idx] = v;
        }
    }

    int tx = tid & 31, ty = tid >> 5;
    const int col = tx * 4;
    float acc[4][4];
#pragma unroll
    for (int i = 0; i < 4; i++)
#pragma unroll
        for (int j = 0; j < 4; j++) acc[i][j] = 0.f;

    for (int kt = 0; kt < DD; kt += KT) {
        __syncthreads();
        {
            const float4* Wf  = (const float4*)(W + kt * NCOL);
            float4*       sWf = (float4*)sW;
            constexpr int T4 = KT * NCOL / 4;
            for (int i = tid; i < T4; i += 256) sWf[i] = Wf[i];
        }
        __syncthreads();
#pragma unroll
        for (int k = 0; k < KT; k++) {
            float4 wv = make_float4(0.f, 0.f, 0.f, 0.f);
            if (col < NCOL) wv = *(const float4*)&sW[k][col];
#pragma unroll
            for (int i = 0; i < 4; i++) {
                float a = sA[ty + i * 8][kt + k];
                acc[i][0] += a * wv.x;
                acc[i][1] += a * wv.y;
                acc[i][2] += a * wv.z;
                acc[i][3] += a * wv.w;
            }
        }
    }

    if (col < NCOL) {
        float4 bv = *(const float4*)&bias[col];
#pragma unroll
        for (int i = 0; i < 4; i++) {
            int row = row0 + ty + i * 8;
            if (row < NN) {
                float4 o;
                o.x = acc[i][0] + bv.x;
                o.y = acc[i][1] + bv.y;
                o.z = acc[i][2] + bv.z;
                o.w = acc[i][3] + bv.w;
                *(float4*)&C[(size_t)row * NCOL + col] = o;
            }
        }
    }
}

// ---------------- fused GAT aggregate + pointwise + emit split ----------------
// warp per destination node; first edge-iteration cached in scalar registers
// (covers deg<=32, i.e. almost all nodes); rare longer rows recompute from L2.
__global__ void aggfuse_k(const float* __restrict__ xh,
                          const float* __restrict__ xlbuf, const float* __restrict__ hbuf,
                          const float* __restrict__ lng, const float* __restrict__ lnb,
                          const float* __restrict__ betas, int first, int slot) {
    int n    = (blockIdx.x * blockDim.x + threadIdx.x) >> 5;
    int lane = threadIdx.x & 31;
    if (n >= NN) return;
    const float* asb = g_as + (size_t)slot * NN;
    const float* adb = g_ad + (size_t)slot * NN;
    int s0 = g_rowptr[n], s1 = g_rowptr[n + 1];
    float adn = adb[n];

    // pass 1: online softmax; scalar-cache the FIRST strided edge of this lane
    int   sc0 = 0;
    float ec0 = 0.f;
    float m = -1e30f, d = 0.f;
    {
        int i = s0 + lane;
        if (i < s1) {
            int s  = g_esrc[i];
            float e = asb[s] + adn;
            e = e > 0.f ? e : 0.2f * e;
            sc0 = s; ec0 = e;
            m = e; d = 1.f;
            for (i += 32; i < s1; i += 32) {
                s = g_esrc[i];
                e = asb[s] + adn;
                e = e > 0.f ? e : 0.2f * e;
                if (e > m) { d = d * __expf(m - e) + 1.f; m = e; }
                else       { d += __expf(e - m); }
            }
        }
    }
#pragma unroll
    for (int o = 16; o; o >>= 1) {
        float mo = __shfl_xor_sync(0xFFFFFFFFu, m, o);
        float do_ = __shfl_xor_sync(0xFFFFFFFFu, d, o);
        if (mo > m) { d = d * __expf(m - mo) + do_; m = mo; }
        else        { d += do_ * __expf(mo - m); }
    }
    float inv = 1.f / (d + 1e-16f);

    // pass 2: weighted gather; iteration 0 from registers, later ones recompute
    float4 ag = make_float4(0.f, 0.f, 0.f, 0.f);
    {
        // iteration 0 (register-cached)
        int base = s0;
        if (base < s1) {
            int idx = base + lane;
            float w = 0.f;
            int   s = sc0;
            if (idx < s1) w = __expf(ec0 - m) * inv;
            int cnt = min(32, s1 - base);
            for (int j = 0; j < cnt; j++) {
                float wj = __shfl_sync(0xFFFFFFFFu, w, j);
                int   sj = __shfl_sync(0xFFFFFFFFu, s, j);
                float4 v = ((const float4*)(xh + (size_t)sj * DD))[lane];
                ag.x += wj * v.x; ag.y += wj * v.y;
                ag.z += wj * v.z; ag.w += wj * v.w;
            }
        }
        // iterations >= 1 (rare: deg > 32) — recompute logits from L2
        for (base = s0 + 32; base < s1; base += 32) {
            int idx = base + lane;
            float w = 0.f;
            int   s = 0;
            if (idx < s1) {
                s = g_esrc[idx];
                float e = asb[s] + adn;
                e = e > 0.f ? e : 0.2f * e;
                w = __expf(e - m) * inv;
            }
            int cnt = min(32, s1 - base);
            for (int j = 0; j < cnt; j++) {
                float wj = __shfl_sync(0xFFFFFFFFu, w, j);
                int   sj = __shfl_sync(0xFFFFFFFFu, s, j);
                float4 v = ((const float4*)(xh + (size_t)sj * DD))[lane];
                ag.x += wj * v.x; ag.y += wj * v.y;
                ag.z += wj * v.z; ag.w += wj * v.w;
            }
        }
    }

    // ---- pointwise (agg stays in registers) ----
    size_t off = (size_t)n * DD;
    float4 xl = ((const float4*)(xlbuf + off))[lane];
    float4 xn;
    xn.x = fmaxf(ag.x + xl.x, 0.f);
    xn.y = fmaxf(ag.y + xl.y, 0.f);
    xn.z = fmaxf(ag.z + xl.z, 0.f);
    xn.w = fmaxf(ag.w + xl.w, 0.f);

    float4 hh = ((const float4*)(hbuf + off))[lane];
    float4 t;
    t.x = hh.x * xn.x; t.y = hh.y * xn.y; t.z = hh.z * xn.z; t.w = hh.w * xn.w;

    float sum = t.x + t.y + t.z + t.w;
#pragma unroll
    for (int o = 16; o; o >>= 1) sum += __shfl_xor_sync(0xFFFFFFFFu, sum, o);
    float mu = sum * (1.f / 128.f);

    float4 dc;
    dc.x = t.x - mu; dc.y = t.y - mu; dc.z = t.z - mu; dc.w = t.w - mu;
    float ss = dc.x * dc.x + dc.y * dc.y + dc.z * dc.z + dc.w * dc.w;
#pragma unroll
    for (int o = 16; o; o >>= 1) ss += __shfl_xor_sync(0xFFFFFFFFu, ss, o);
    float rs = rsqrtf(ss * (1.f / 128.f) + 1e-5f);

    float4 g  = ((const float4*)lng)[lane];
    float4 b  = ((const float4*)lnb)[lane];
    float4 be = ((const float4*)betas)[lane];
    be.x = 1.f / (1.f + __expf(-be.x));
    be.y = 1.f / (1.f + __expf(-be.y));
    be.z = 1.f / (1.f + __expf(-be.z));
    be.w = 1.f / (1.f + __expf(-be.w));

    float4 y;
    y.x = dc.x * rs * g.x + b.x;
    y.y = dc.y * rs * g.y + b.y;
    y.z = dc.z * rs * g.z + b.z;
    y.w = dc.w * rs * g.w + b.w;

    float4 xo;
    xo.x = (1.f - be.x) * y.x + be.x * xn.x;
    xo.y = (1.f - be.y) * y.y + be.y * xn.y;
    xo.z = (1.f - be.z) * y.z + be.z * xn.z;
    xo.w = (1.f - be.w) * y.w + be.w * xn.w;

    // emit bf16 split of new x
    {
        uint32_t hx, lx, hy, ly, hz, lz, hw, lw;
        bsplit(xo.x, hx, lx); bsplit(xo.y, hy, ly);
        bsplit(xo.z, hz, lz); bsplit(xo.w, hw, lw);
        size_t o2 = (size_t)n * 64 + 2 * lane;
        g_ah[o2]     = hx | (hy << 16);
        g_ah[o2 + 1] = hz | (hw << 16);
        g_al[o2]     = lx | (ly << 16);
        g_al[o2 + 1] = lz | (lw << 16);
    }

    if (first) {
        ((float4*)(g_xlocal + off))[lane] = xo;
    } else {
        float4 p = ((const float4*)(g_xlocal + off))[lane];
        p.x += xo.x; p.y += xo.y; p.z += xo.z; p.w += xo.w;
        ((float4*)(g_xlocal + off))[lane] = p;
    }

    // zero the OTHER attention slot (used by the next layer's GEMM)
    if (lane == 0) {
        int os = slot ^ 1;
        g_as[(size_t)os * NN + n] = 0.f;
        g_ad[(size_t)os * NN + n] = 0.f;
    }
}

// ---------------- host ----------------
extern "C" void kernel_launch(void* const* d_in, const int* in_sizes, int n_in,
                              void* d_out, int out_size) {
    const float* x       = (const float*)d_in[0];
    const int*   ei32    = (const int*)d_in[1];
    const float* W_in    = (const float*)d_in[2];
    const float* b_in    = (const float*)d_in[3];
    const float* W_h     = (const float*)d_in[4];
    const float* b_h     = (const float*)d_in[5];
    const float* W_gat   = (const float*)d_in[6];
    const float* att_src = (const float*)d_in[7];
    const float* att_dst = (const float*)d_in[8];
    const float* W_l     = (const float*)d_in[9];
    const float* b_l     = (const float*)d_in[10];
    const float* ln_g    = (const float*)d_in[11];
    const float* ln_b    = (const float*)d_in[12];
    const float* betas   = (const float*)d_in[13];
    const float* W_pred  = (const float*)d_in[14];
    const float* b_pred  = (const float*)d_in[15];
    float*       out     = (float*)d_out;

    float *ph, *pxh, *pxl, *pxloc;
    uint32_t *pinh, *pinl, *pah, *pal;
    cudaGetSymbolAddress((void**)&ph,    g_h);
    cudaGetSymbolAddress((void**)&pxh,   g_xh);
    cudaGetSymbolAddress((void**)&pxl,   g_xl);
    cudaGetSymbolAddress((void**)&pxloc, g_xlocal);
    cudaGetSymbolAddress((void**)&pinh,  g_inh);
    cudaGetSymbolAddress((void**)&pinl,  g_inl);
    cudaGetSymbolAddress((void**)&pah,   g_ah);
    cudaGetSymbolAddress((void**)&pal,   g_al);

    const int dynsmem = 2 * 4 * SZW * 4;   // 81920 bytes
    static cudaStream_t s_side = nullptr;
    static cudaEvent_t  ev_fork = nullptr, ev_join = nullptr;
    if (!s_side) {
        cudaFuncSetAttribute(mma_gemm_k, cudaFuncAttributeMaxDynamicSharedMemorySize, dynsmem);
        cudaStreamCreateWithFlags(&s_side, cudaStreamNonBlocking);
        cudaEventCreateWithFlags(&ev_fork, cudaEventDisableTiming);
        cudaEventCreateWithFlags(&ev_join, cudaEventDisableTiming);
    }

    dim3 gE((EE + 255) / 256);
    dim3 gN((NN + 255) / 256);
    dim3 gW((NN + 7) / 8);
    dim3 gG((NN + 31) / 32);
    dim3 gM((NN + 127) / 128, 1);
    dim3 gM3((NN + 127) / 128, 3);

    // zeroing on main (prereq for BOTH branches)
    zero_k<<<gN, 256>>>();

    // fork: CSR build on side stream
    cudaEventRecord(ev_fork, 0);
    cudaStreamWaitEvent(s_side, ev_fork, 0);
    decode_deg_k<<<gE, 256, 0, s_side>>>(ei32);
    pscan_k<<<NSB, SB, 0, s_side>>>();
    bscan_k<<<1, 128, 0, s_side>>>();
    addoff_k<<<gN, 256, 0, s_side>>>();
    scat_k<<<gE, 256, 0, s_side>>>();
    cudaEventRecord(ev_join, s_side);

    // main: splits + dense prologue (independent of CSR)
    split_w_k<<<(10 * 64 * 128 + 255) / 256, 256>>>(W_in, W_h, W_gat, W_l);
    split_x_k<<<(NN * 32 + 255) / 256, 256>>>(x);

    // input projection: x @ W_in + b_in -> split only
    {
        GemmArgs2 a{};
        a.wslot[0] = 0; a.bias[0] = b_in; a.out[0] = nullptr; a.epi[0] = 1;
        a.emit_split = 1; a.attn_w = -1;
        mma_gemm_k<<<gM, 256, dynsmem>>>(pinh, pinl, a);
    }

    // layer 0 GEMM is also CSR-independent
    {
        GemmArgs2 a{};
        a.wslot[0] = 1; a.bias[0] = b_h; a.out[0] = ph;  a.epi[0] = 2;
        a.wslot[1] = 2; a.bias[1] = nullptr; a.out[1] = pxh; a.epi[1] = 0;
        a.wslot[2] = 3; a.bias[2] = b_l; a.out[2] = pxl; a.epi[2] = 1;
        a.emit_split = 0;
        a.attn_w = 1; a.attn_slot = 0;
        a.attn_a = att_src; a.attn_d = att_dst;
        mma_gemm_k<<<gM3, 256, dynsmem>>>(pah, pal, a);
    }

    // join: aggfuse needs the CSR
    cudaStreamWaitEvent(0, ev_join, 0);

    for (int i = 0; i < LL; i++) {
        if (i > 0) {
            GemmArgs2 a{};
            a.wslot[0] = 1 + 3 * i;     a.bias[0] = b_h + i * DD; a.out[0] = ph;  a.epi[0] = 2;
            a.wslot[1] = 1 + 3 * i + 1; a.bias[1] = nullptr;      a.out[1] = pxh; a.epi[1] = 0;
            a.wslot[2] = 1 + 3 * i + 2; a.bias[2] = b_l + i * DD; a.out[2] = pxl; a.epi[2] = 1;
            a.emit_split = 0;
            a.attn_w = 1; a.attn_slot = i & 1;
            a.attn_a = att_src + i * DD; a.attn_d = att_dst + i * DD;
            mma_gemm_k<<<gM3, 256, dynsmem>>>(pah, pal, a);
        }

        aggfuse_k<<<gW, 256>>>(pxh, pxl, ph,
                               ln_g + i * DD, ln_b + i * DD, betas + i * DD,
                               i == 0, i & 1);
    }

    gemm_small_k<OUTD><<<gG, 256>>>(pxloc, W_pred, b_pred, out);
}

// round 15
// speedup vs baseline: 1.0267x; 1.0140x over previous
#include <cuda_runtime.h>
#include <cuda_bf16.h>
#include <math.h>
#include <stdint.h>

#define NN   50000
#define EE   800000
#define DD   128
#define LL   3
#define OUTD 40
#define SB   512
#define NSB  ((NN + SB - 1) / SB)   // 98
#define PADW 20
#define SZW  (128 * PADW)           // words per smem tile (2560)

// ---------------- scratch (device globals; no allocation allowed) ----------------
__device__ float    g_h[NN * DD];
__device__ float    g_xh[NN * DD];
__device__ float    g_xl[NN * DD];
__device__ float    g_xlocal[NN * DD];
__device__ float    g_as[2 * NN];   // double-buffered attention logit accumulators
__device__ float    g_ad[2 * NN];
__device__ float2   g_ewp[EE];      // packed (logit, src-as-float) per edge
__device__ int      g_deg[NN];
__device__ int      g_fill[NN];
__device__ int      g_rowptr[NN + 1];
__device__ int      g_esrc[EE];
__device__ int      g_src[EE];
__device__ int      g_dst[EE];
__device__ int      g_bsum[NSB];
__device__ int      g_boff[128];
// packed bf16 pairs (hi/lo) along k: [row][64 words]
__device__ uint32_t g_inh[NN * 64];
__device__ uint32_t g_inl[NN * 64];
__device__ uint32_t g_ah[NN * 64];
__device__ uint32_t g_al[NN * 64];
// pre-split weights: [wslot][n][64 words], 10 slots
__device__ uint32_t g_wsh[10 * 128 * 64];
__device__ uint32_t g_wsl[10 * 128 * 64];

__device__ __forceinline__ void bsplit(float v, uint32_t& h, uint32_t& l) {
    __nv_bfloat16 bh = __float2bfloat16_rn(v);
    float r = v - __bfloat162float(bh);
    __nv_bfloat16 bl = __float2bfloat16_rn(r);
    h = (uint32_t)__bfloat16_as_ushort(bh);
    l = (uint32_t)__bfloat16_as_ushort(bl);
}

__device__ __forceinline__ void cp16(void* dst_s, const void* src_g) {
    uint32_t d = (uint32_t)__cvta_generic_to_shared(dst_s);
    asm volatile("cp.async.cg.shared.global [%0], [%1], 16;" :: "r"(d), "l"(src_g));
}

// ---------------- edge decode + degree histogram (fused) ----------------
__global__ void decode_deg_k(const int* __restrict__ ei32) {
    bool is64 = (ei32[1] == 0 && ei32[3] == 0 && ei32[5] == 0 && ei32[7] == 0);
    int e = blockIdx.x * blockDim.x + threadIdx.x;
    if (e < EE) {
        int s, d;
        if (is64) {
            s = ei32[2 * (size_t)e];
            d = ei32[2 * ((size_t)EE + e)];
        } else {
            s = ei32[e];
            d = ei32[EE + e];
        }
        g_src[e] = s;
        g_dst[e] = d;
        atomicAdd(&g_deg[d], 1);
    }
}

__global__ void zero_k() {
    int i = blockIdx.x * blockDim.x + threadIdx.x;
    if (i < NN) {
        g_deg[i] = 0; g_fill[i] = 0;
        g_as[i] = 0.f; g_ad[i] = 0.f;
        g_as[NN + i] = 0.f; g_ad[NN + i] = 0.f;
    }
}

__global__ void pscan_k() {
    __shared__ int sh[SB];
    int t = threadIdx.x;
    int i = blockIdx.x * SB + t;
    int v = (i < NN) ? g_deg[i] : 0;
    sh[t] = v;
    __syncthreads();
    for (int o = 1; o < SB; o <<= 1) {
        int a = (t >= o) ? sh[t - o] : 0;
        __syncthreads();
        sh[t] += a;
        __syncthreads();
    }
    if (i < NN) g_rowptr[i] = sh[t] - v;
    if (t == SB - 1) g_bsum[blockIdx.x] = sh[t];
}

__global__ void bscan_k() {
    __shared__ int sh[128];
    int t = threadIdx.x;
    int v = (t < NSB) ? g_bsum[t] : 0;
    sh[t] = v;
    __syncthreads();
    for (int o = 1; o < 128; o <<= 1) {
        int a = (t >= o) ? sh[t - o] : 0;
        __syncthreads();
        sh[t] += a;
        __syncthreads();
    }
    g_boff[t] = sh[t] - v;
}

__global__ void addoff_k() {
    int i = blockIdx.x * blockDim.x + threadIdx.x;
    if (i < NN) g_rowptr[i] += g_boff[i / SB];
    if (i == 0) g_rowptr[NN] = EE;
}

__global__ void scat_k() {
    int e = blockIdx.x * blockDim.x + threadIdx.x;
    if (e < EE) {
        int d = g_dst[e];
        int p = g_rowptr[d] + atomicAdd(&g_fill[d], 1);
        g_esrc[p] = g_src[e];
    }
}

// ---------------- one-time weight split ----------------
__global__ void split_w_k(const float* __restrict__ W_in, const float* __restrict__ W_h,
                          const float* __restrict__ W_gat, const float* __restrict__ W_l) {
    int idx = blockIdx.x * blockDim.x + threadIdx.x;   // 10*64*128
    if (idx >= 10 * 64 * 128) return;
    int w   = idx >> 13;
    int kw  = (idx >> 7) & 63;
    int n   = idx & 127;
    const float* base;
    if (w == 0) base = W_in;
    else {
        int layer = (w - 1) / 3, t = (w - 1) % 3;
        base = (t == 0 ? W_h : t == 1 ? W_gat : W_l) + (size_t)layer * DD * DD;
    }
    float v0 = base[(size_t)(2 * kw) * DD + n];
    float v1 = base[(size_t)(2 * kw + 1) * DD + n];
    uint32_t h0, l0, h1, l1;
    bsplit(v0, h0, l0); bsplit(v1, h1, l1);
    g_wsh[(size_t)w * 8192 + n * 64 + kw] = h0 | (h1 << 16);
    g_wsl[(size_t)w * 8192 + n * 64 + kw] = l0 | (l1 << 16);
}

// ---------------- one-time input split ----------------
__global__ void split_x_k(const float* __restrict__ x) {
    int t = blockIdx.x * blockDim.x + threadIdx.x;     // NN*32
    if (t >= NN * 32) return;
    int row = t >> 5, q = t & 31;
    float4 v = ((const float4*)x)[(size_t)row * 32 + q];
    uint32_t hx, lx, hy, ly, hz, lz, hw, lw;
    bsplit(v.x, hx, lx); bsplit(v.y, hy, ly);
    bsplit(v.z, hz, lz); bsplit(v.w, hw, lw);
    size_t o = (size_t)row * 64 + 2 * q;
    g_inh[o]     = hx | (hy << 16);
    g_inh[o + 1] = hz | (hw << 16);
    g_inl[o]     = lx | (ly << 16);
    g_inl[o + 1] = lz | (lw << 16);
}

// ---------------- bf16x3 GEMM, cp.async double-buffered, fused attn logits ----------------
struct GemmArgs2 {
    int          wslot[3];
    const float* bias[3];
    float*       out[3];
    int          epi[3];     // 0 none, 1 bias, 2 bias+relu
    int          emit_split;
    int          attn_w;     // which w computes attention logits (-1 = none)
    int          attn_slot;  // accumulator slot (0/1)
    const float* attn_a;
    const float* attn_d;
};

extern __shared__ uint32_t smem_dyn[];

__global__ __launch_bounds__(256, 2)
void mma_gemm_k(const uint32_t* __restrict__ Ah, const uint32_t* __restrict__ Al,
                GemmArgs2 args) {
    const int tid  = threadIdx.x;
    const int lane = tid & 31;
    const int wid  = tid >> 5;
    const int wm   = (wid >> 1) * 32;
    const int wn   = (wid & 1) * 64;
    const int row0 = blockIdx.x * 128;
    const int w    = blockIdx.y;

    const uint32_t* Wh = g_wsh + (size_t)args.wslot[w] * 8192;
    const uint32_t* Wl = g_wsl + (size_t)args.wslot[w] * 8192;

    const int ar = lane >> 2;
    const int ac = lane & 3;

    float acc[2][8][4];
#pragma unroll
    for (int i = 0; i < 2; i++)
#pragma unroll
        for (int j = 0; j < 8; j++)
#pragma unroll
            for (int c = 0; c < 4; c++) acc[i][j][c] = 0.f;

    auto stage = [&](int kc, int s) {
        uint32_t* bAh = smem_dyn + s * 4 * SZW;
        uint32_t* bAl = bAh + SZW;
        uint32_t* bWh = bAl + SZW;
        uint32_t* bWl = bWh + SZW;
        const int kwc = kc >> 1;
#pragma unroll
        for (int t = tid; t < 512; t += 256) {
            int m = t >> 2, q = t & 3;
            int row = row0 + m;
            uint32_t* dh = &bAh[m * PADW + 4 * q];
            uint32_t* dl = &bAl[m * PADW + 4 * q];
            if (row < NN) {
                size_t o = (size_t)row * 64 + kwc + 4 * q;
                cp16(dh, &Ah[o]);
                cp16(dl, &Al[o]);
            } else {
                *(uint4*)dh = make_uint4(0, 0, 0, 0);
                *(uint4*)dl = make_uint4(0, 0, 0, 0);
            }
        }
#pragma unroll
        for (int t = tid; t < 512; t += 256) {
            int n = t >> 2, q = t & 3;
            size_t o = (size_t)n * 64 + kwc + 4 * q;
            cp16(&bWh[n * PADW + 4 * q], &Wh[o]);
            cp16(&bWl[n * PADW + 4 * q], &Wl[o]);
        }
        asm volatile("cp.async.commit_group;");
    };

    stage(0, 0);

#pragma unroll
    for (int c = 0; c < 4; c++) {
        if (c < 3) stage((c + 1) * 32, (c + 1) & 1);
        if (c < 3) asm volatile("cp.async.wait_group 1;");
        else       asm volatile("cp.async.wait_group 0;");
        __syncthreads();

        const uint32_t* bAh = smem_dyn + (c & 1) * 4 * SZW;
        const uint32_t* bAl = bAh + SZW;
        const uint32_t* bWh = bAl + SZW;
        const uint32_t* bWl = bWh + SZW;

#pragma unroll
        for (int s = 0; s < 2; s++) {
            const int kb = s * 8;
            uint32_t ah[2][4], al[2][4];
#pragma unroll
            for (int i = 0; i < 2; i++) {
                int m = wm + i * 16 + ar;
                ah[i][0] = bAh[m * PADW + kb + ac];
                ah[i][1] = bAh[(m + 8) * PADW + kb + ac];
                ah[i][2] = bAh[m * PADW + kb + ac + 4];
                ah[i][3] = bAh[(m + 8) * PADW + kb + ac + 4];
                al[i][0] = bAl[m * PADW + kb + ac];
                al[i][1] = bAl[(m + 8) * PADW + kb + ac];
                al[i][2] = bAl[m * PADW + kb + ac + 4];
                al[i][3] = bAl[(m + 8) * PADW + kb + ac + 4];
            }
#pragma unroll
            for (int j = 0; j < 8; j++) {
                int n = wn + j * 8 + ar;
                uint32_t bh0 = bWh[n * PADW + kb + ac];
                uint32_t bh1 = bWh[n * PADW + kb + ac + 4];
                uint32_t bl0 = bWl[n * PADW + kb + ac];
                uint32_t bl1 = bWl[n * PADW + kb + ac + 4];
#pragma unroll
                for (int i = 0; i < 2; i++) {
                    asm volatile(
                        "mma.sync.aligned.m16n8k16.row.col.f32.bf16.bf16.f32 "
                        "{%0,%1,%2,%3}, {%4,%5,%6,%7}, {%8,%9}, {%0,%1,%2,%3};"
                        : "+f"(acc[i][j][0]), "+f"(acc[i][j][1]),
                          "+f"(acc[i][j][2]), "+f"(acc[i][j][3])
                        : "r"(ah[i][0]), "r"(ah[i][1]), "r"(ah[i][2]), "r"(ah[i][3]),
                          "r"(bh0), "r"(bh1));
                    asm volatile(
                        "mma.sync.aligned.m16n8k16.row.col.f32.bf16.bf16.f32 "
                        "{%0,%1,%2,%3}, {%4,%5,%6,%7}, {%8,%9}, {%0,%1,%2,%3};"
                        : "+f"(acc[i][j][0]), "+f"(acc[i][j][1]),
                          "+f"(acc[i][j][2]), "+f"(acc[i][j][3])
                        : "r"(ah[i][0]), "r"(ah[i][1]), "r"(ah[i][2]), "r"(ah[i][3]),
                          "r"(bl0), "r"(bl1));
                    asm volatile(
                        "mma.sync.aligned.m16n8k16.row.col.f32.bf16.bf16.f32 "
                        "{%0,%1,%2,%3}, {%4,%5,%6,%7}, {%8,%9}, {%0,%1,%2,%3};"
                        : "+f"(acc[i][j][0]), "+f"(acc[i][j][1]),
                          "+f"(acc[i][j][2]), "+f"(acc[i][j][3])
                        : "r"(al[i][0]), "r"(al[i][1]), "r"(al[i][2]), "r"(al[i][3]),
                          "r"(bh0), "r"(bh1));
                }
            }
        }
        __syncthreads();
    }

    // ---- epilogue ----
    const int epi = args.epi[w];
    const float* bias = args.bias[w];
    float* out = args.out[w];
    const int emit = args.emit_split;
    const bool do_attn = (w == args.attn_w);
    float* asb = g_as + (size_t)args.attn_slot * NN;
    float* adb = g_ad + (size_t)args.attn_slot * NN;
    float ps[2] = {0.f, 0.f}, pd[2] = {0.f, 0.f};
    float ps2[2] = {0.f, 0.f}, pd2[2] = {0.f, 0.f};

#pragma unroll
    for (int i = 0; i < 2; i++) {
#pragma unroll
        for (int j = 0; j < 8; j++) {
            int cc = wn + j * 8 + ac * 2;
            float bx = 0.f, by = 0.f;
            if (epi >= 1) { bx = bias[cc]; by = bias[cc + 1]; }
            float c0 = acc[i][j][0] + bx, c1 = acc[i][j][1] + by;
            float c2 = acc[i][j][2] + bx, c3 = acc[i][j][3] + by;
            if (epi == 2) {
                c0 = fmaxf(c0, 0.f); c1 = fmaxf(c1, 0.f);
                c2 = fmaxf(c2, 0.f); c3 = fmaxf(c3, 0.f);
            }
            if (do_attn) {
                float a0 = args.attn_a[cc], a1 = args.attn_a[cc + 1];
                float d0 = args.attn_d[cc], d1 = args.attn_d[cc + 1];
                ps[i]  += c0 * a0 + c1 * a1;
                pd[i]  += c0 * d0 + c1 * d1;
                ps2[i] += c2 * a0 + c3 * a1;
                pd2[i] += c2 * d0 + c3 * d1;
            }
            int r0 = row0 + wm + i * 16 + ar;
            if (out) {
                if (r0 < NN)     *(float2*)&out[(size_t)r0 * DD + cc]       = make_float2(c0, c1);
                if (r0 + 8 < NN) *(float2*)&out[(size_t)(r0 + 8) * DD + cc] = make_float2(c2, c3);
            }
            if (emit) {
                uint32_t h0, l0, h1, l1;
                if (r0 < NN) {
                    bsplit(c0, h0, l0); bsplit(c1, h1, l1);
                    g_ah[(size_t)r0 * 64 + (cc >> 1)] = h0 | (h1 << 16);
                    g_al[(size_t)r0 * 64 + (cc >> 1)] = l0 | (l1 << 16);
                }
                if (r0 + 8 < NN) {
                    bsplit(c2, h0, l0); bsplit(c3, h1, l1);
                    g_ah[(size_t)(r0 + 8) * 64 + (cc >> 1)] = h0 | (h1 << 16);
                    g_al[(size_t)(r0 + 8) * 64 + (cc >> 1)] = l0 | (l1 << 16);
                }
            }
        }
    }

    if (do_attn) {
#pragma unroll
        for (int i = 0; i < 2; i++) {
#pragma unroll
            for (int o = 1; o <= 2; o <<= 1) {
                ps[i]  += __shfl_xor_sync(0xFFFFFFFFu, ps[i],  o);
                pd[i]  += __shfl_xor_sync(0xFFFFFFFFu, pd[i],  o);
                ps2[i] += __shfl_xor_sync(0xFFFFFFFFu, ps2[i], o);
                pd2[i] += __shfl_xor_sync(0xFFFFFFFFu, pd2[i], o);
            }
            if (ac == 0) {
                int r0 = row0 + wm + i * 16 + ar;
                if (r0 < NN) {
                    atomicAdd(&asb[r0], ps[i]);
                    atomicAdd(&adb[r0], pd[i]);
                }
                if (r0 + 8 < NN) {
                    atomicAdd(&asb[r0 + 8], ps2[i]);
                    atomicAdd(&adb[r0 + 8], pd2[i]);
                }
            }
        }
    }
}

// ---------------- small FFMA GEMM for the prediction head (NCOL=40) ----------------
template <int NCOL>
__global__ void gemm_small_k(const float* __restrict__ A, const float* __restrict__ W,
                             const float* __restrict__ bias, float* __restrict__ C) {
    constexpr int ROWS = 32;
    constexpr int KT   = 32;
    __shared__ float sA[ROWS][DD];
    __shared__ float sW[KT][NCOL];
    int tid  = threadIdx.x;
    int row0 = blockIdx.x * ROWS;

    {
        const float4* Af  = (const float4*)A;
        float4*       sAf = (float4*)sA;
#pragma unroll
        for (int i = 0; i < 4; i++) {
            int idx = tid + i * 256;
            int r = idx >> 5, c = idx & 31;
            float4 v = make_float4(0.f, 0.f, 0.f, 0.f);
            if (row0 + r < NN) v = Af[(size_t)(row0 + r) * 32 + c];
            sAf[idx] = v;
        }
    }

    int tx = tid & 31, ty = tid >> 5;
    const int col = tx * 4;
    float acc[4][4];
#pragma unroll
    for (int i = 0; i < 4; i++)
#pragma unroll
        for (int j = 0; j < 4; j++) acc[i][j] = 0.f;

    for (int kt = 0; kt < DD; kt += KT) {
        __syncthreads();
        {
            const float4* Wf  = (const float4*)(W + kt * NCOL);
            float4*       sWf = (float4*)sW;
            constexpr int T4 = KT * NCOL / 4;
            for (int i = tid; i < T4; i += 256) sWf[i] = Wf[i];
        }
        __syncthreads();
#pragma unroll
        for (int k = 0; k < KT; k++) {
            float4 wv = make_float4(0.f, 0.f, 0.f, 0.f);
            if (col < NCOL) wv = *(const float4*)&sW[k][col];
#pragma unroll
            for (int i = 0; i < 4; i++) {
                float a = sA[ty + i * 8][kt + k];
                acc[i][0] += a * wv.x;
                acc[i][1] += a * wv.y;
                acc[i][2] += a * wv.z;
                acc[i][3] += a * wv.w;
            }
        }
    }

    if (col < NCOL) {
        float4 bv = *(const float4*)&bias[col];
#pragma unroll
        for (int i = 0; i < 4; i++) {
            int row = row0 + ty + i * 8;
            if (row < NN) {
                float4 o;
                o.x = acc[i][0] + bv.x;
                o.y = acc[i][1] + bv.y;
                o.z = acc[i][2] + bv.z;
                o.w = acc[i][3] + bv.w;
                *(float4*)&C[(size_t)row * NCOL + col] = o;
            }
        }
    }
}

// ---------------- fused GAT aggregate + pointwise + emit split ----------------
// warp per destination node (Round-12 structure: g_ewp packed logit+src cache)
__global__ void aggfuse_k(const float* __restrict__ xh,
                          const float* __restrict__ xlbuf, const float* __restrict__ hbuf,
                          const float* __restrict__ lng, const float* __restrict__ lnb,
                          const float* __restrict__ betas, int first, int slot) {
    int n    = (blockIdx.x * blockDim.x + threadIdx.x) >> 5;
    int lane = threadIdx.x & 31;
    if (n >= NN) return;
    const float* asb = g_as + (size_t)slot * NN;
    const float* adb = g_ad + (size_t)slot * NN;
    int s0 = g_rowptr[n], s1 = g_rowptr[n + 1];
    float adn = adb[n];

    // pass 1: online softmax; cache (logit, src) packed per edge
    float m = -1e30f, d = 0.f;
    for (int i = s0 + lane; i < s1; i += 32) {
        int s  = g_esrc[i];
        float e = asb[s] + adn;
        e = e > 0.f ? e : 0.2f * e;
        g_ewp[i] = make_float2(e, __int_as_float(s));
        if (e > m) { d = d * __expf(m - e) + 1.f; m = e; }
        else       { d += __expf(e - m); }
    }
#pragma unroll
    for (int o = 16; o; o >>= 1) {
        float mo = __shfl_xor_sync(0xFFFFFFFFu, m, o);
        float do_ = __shfl_xor_sync(0xFFFFFFFFu, d, o);
        if (mo > m) { d = d * __expf(m - mo) + do_; m = mo; }
        else        { d += do_ * __expf(mo - m); }
    }
    float inv = 1.f / (d + 1e-16f);

    // pass 2: one 8B load per edge (logit + src), weighted gather
    float4 ag = make_float4(0.f, 0.f, 0.f, 0.f);
    for (int base = s0; base < s1; base += 32) {
        int idx = base + lane;
        float w = 0.f;
        int   s = 0;
        if (idx < s1) {
            float2 p = g_ewp[idx];
            s = __float_as_int(p.y);
            w = __expf(p.x - m) * inv;
        }
        int cnt = min(32, s1 - base);
        for (int j = 0; j < cnt; j++) {
            float wj = __shfl_sync(0xFFFFFFFFu, w, j);
            int   sj = __shfl_sync(0xFFFFFFFFu, s, j);
            float4 v = ((const float4*)(xh + (size_t)sj * DD))[lane];
            ag.x += wj * v.x; ag.y += wj * v.y;
            ag.z += wj * v.z; ag.w += wj * v.w;
        }
    }

    // ---- pointwise (agg stays in registers) ----
    size_t off = (size_t)n * DD;
    float4 xl = ((const float4*)(xlbuf + off))[lane];
    float4 xn;
    xn.x = fmaxf(ag.x + xl.x, 0.f);
    xn.y = fmaxf(ag.y + xl.y, 0.f);
    xn.z = fmaxf(ag.z + xl.z, 0.f);
    xn.w = fmaxf(ag.w + xl.w, 0.f);

    float4 hh = ((const float4*)(hbuf + off))[lane];
    float4 t;
    t.x = hh.x * xn.x; t.y = hh.y * xn.y; t.z = hh.z * xn.z; t.w = hh.w * xn.w;

    float sum = t.x + t.y + t.z + t.w;
#pragma unroll
    for (int o = 16; o; o >>= 1) sum += __shfl_xor_sync(0xFFFFFFFFu, sum, o);
    float mu = sum * (1.f / 128.f);

    float4 dc;
    dc.x = t.x - mu; dc.y = t.y - mu; dc.z = t.z - mu; dc.w = t.w - mu;
    float ss = dc.x * dc.x + dc.y * dc.y + dc.z * dc.z + dc.w * dc.w;
#pragma unroll
    for (int o = 16; o; o >>= 1) ss += __shfl_xor_sync(0xFFFFFFFFu, ss, o);
    float rs = rsqrtf(ss * (1.f / 128.f) + 1e-5f);

    float4 g  = ((const float4*)lng)[lane];
    float4 b  = ((const float4*)lnb)[lane];
    float4 be = ((const float4*)betas)[lane];
    be.x = 1.f / (1.f + __expf(-be.x));
    be.y = 1.f / (1.f + __expf(-be.y));
    be.z = 1.f / (1.f + __expf(-be.z));
    be.w = 1.f / (1.f + __expf(-be.w));

    float4 y;
    y.x = dc.x * rs * g.x + b.x;
    y.y = dc.y * rs * g.y + b.y;
    y.z = dc.z * rs * g.z + b.z;
    y.w = dc.w * rs * g.w + b.w;

    float4 xo;
    xo.x = (1.f - be.x) * y.x + be.x * xn.x;
    xo.y = (1.f - be.y) * y.y + be.y * xn.y;
    xo.z = (1.f - be.z) * y.z + be.z * xn.z;
    xo.w = (1.f - be.w) * y.w + be.w * xn.w;

    // emit bf16 split of new x
    {
        uint32_t hx, lx, hy, ly, hz, lz, hw, lw;
        bsplit(xo.x, hx, lx); bsplit(xo.y, hy, ly);
        bsplit(xo.z, hz, lz); bsplit(xo.w, hw, lw);
        size_t o2 = (size_t)n * 64 + 2 * lane;
        g_ah[o2]     = hx | (hy << 16);
        g_ah[o2 + 1] = hz | (hw << 16);
        g_al[o2]     = lx | (ly << 16);
        g_al[o2 + 1] = lz | (lw << 16);
    }

    if (first) {
        ((float4*)(g_xlocal + off))[lane] = xo;
    } else {
        float4 p = ((const float4*)(g_xlocal + off))[lane];
        p.x += xo.x; p.y += xo.y; p.z += xo.z; p.w += xo.w;
        ((float4*)(g_xlocal + off))[lane] = p;
    }

    // zero the OTHER attention slot (used by the next layer's GEMM)
    if (lane == 0) {
        int os = slot ^ 1;
        g_as[(size_t)os * NN + n] = 0.f;
        g_ad[(size_t)os * NN + n] = 0.f;
    }
}

// ---------------- host ----------------
extern "C" void kernel_launch(void* const* d_in, const int* in_sizes, int n_in,
                              void* d_out, int out_size) {
    const float* x       = (const float*)d_in[0];
    const int*   ei32    = (const int*)d_in[1];
    const float* W_in    = (const float*)d_in[2];
    const float* b_in    = (const float*)d_in[3];
    const float* W_h     = (const float*)d_in[4];
    const float* b_h     = (const float*)d_in[5];
    const float* W_gat   = (const float*)d_in[6];
    const float* att_src = (const float*)d_in[7];
    const float* att_dst = (const float*)d_in[8];
    const float* W_l     = (const float*)d_in[9];
    const float* b_l     = (const float*)d_in[10];
    const float* ln_g    = (const float*)d_in[11];
    const float* ln_b    = (const float*)d_in[12];
    const float* betas   = (const float*)d_in[13];
    const float* W_pred  = (const float*)d_in[14];
    const float* b_pred  = (const float*)d_in[15];
    float*       out     = (float*)d_out;

    float *ph, *pxh, *pxl, *pxloc;
    uint32_t *pinh, *pinl, *pah, *pal;
    cudaGetSymbolAddress((void**)&ph,    g_h);
    cudaGetSymbolAddress((void**)&pxh,   g_xh);
    cudaGetSymbolAddress((void**)&pxl,   g_xl);
    cudaGetSymbolAddress((void**)&pxloc, g_xlocal);
    cudaGetSymbolAddress((void**)&pinh,  g_inh);
    cudaGetSymbolAddress((void**)&pinl,  g_inl);
    cudaGetSymbolAddress((void**)&pah,   g_ah);
    cudaGetSymbolAddress((void**)&pal,   g_al);

    const int dynsmem = 2 * 4 * SZW * 4;   // 81920 bytes
    static cudaStream_t s_side = nullptr;
    static cudaEvent_t  ev_fork = nullptr, ev_join = nullptr;
    if (!s_side) {
        cudaFuncSetAttribute(mma_gemm_k, cudaFuncAttributeMaxDynamicSharedMemorySize, dynsmem);
        cudaStreamCreateWithFlags(&s_side, cudaStreamNonBlocking);
        cudaEventCreateWithFlags(&ev_fork, cudaEventDisableTiming);
        cudaEventCreateWithFlags(&ev_join, cudaEventDisableTiming);
    }

    dim3 gE((EE + 255) / 256);
    dim3 gN((NN + 255) / 256);
    dim3 gW((NN + 7) / 8);
    dim3 gG((NN + 31) / 32);
    dim3 gM((NN + 127) / 128, 1);
    dim3 gM3((NN + 127) / 128, 3);

    // zeroing on main (prereq for BOTH branches)
    zero_k<<<gN, 256>>>();

    // fork: CSR build on side stream
    cudaEventRecord(ev_fork, 0);
    cudaStreamWaitEvent(s_side, ev_fork, 0);
    decode_deg_k<<<gE, 256, 0, s_side>>>(ei32);
    pscan_k<<<NSB, SB, 0, s_side>>>();
    bscan_k<<<1, 128, 0, s_side>>>();
    addoff_k<<<gN, 256, 0, s_side>>>();
    scat_k<<<gE, 256, 0, s_side>>>();
    cudaEventRecord(ev_join, s_side);

    // main: splits + dense prologue (independent of CSR)
    split_w_k<<<(10 * 64 * 128 + 255) / 256, 256>>>(W_in, W_h, W_gat, W_l);
    split_x_k<<<(NN * 32 + 255) / 256, 256>>>(x);

    // input projection: x @ W_in + b_in -> split only
    {
        GemmArgs2 a{};
        a.wslot[0] = 0; a.bias[0] = b_in; a.out[0] = nullptr; a.epi[0] = 1;
        a.emit_split = 1; a.attn_w = -1;
        mma_gemm_k<<<gM, 256, dynsmem>>>(pinh, pinl, a);
    }

    // layer 0 GEMM is also CSR-independent
    {
        GemmArgs2 a{};
        a.wslot[0] = 1; a.bias[0] = b_h; a.out[0] = ph;  a.epi[0] = 2;
        a.wslot[1] = 2; a.bias[1] = nullptr; a.out[1] = pxh; a.epi[1] = 0;
        a.wslot[2] = 3; a.bias[2] = b_l; a.out[2] = pxl; a.epi[2] = 1;
        a.emit_split = 0;
        a.attn_w = 1; a.attn_slot = 0;
        a.attn_a = att_src; a.attn_d = att_dst;
        mma_gemm_k<<<gM3, 256, dynsmem>>>(pah, pal, a);
    }

    // join: aggfuse needs the CSR
    cudaStreamWaitEvent(0, ev_join, 0);

    for (int i = 0; i < LL; i++) {
        if (i > 0) {
            GemmArgs2 a{};
            a.wslot[0] = 1 + 3 * i;     a.bias[0] = b_h + i * DD; a.out[0] = ph;  a.epi[0] = 2;
            a.wslot[1] = 1 + 3 * i + 1; a.bias[1] = nullptr;      a.out[1] = pxh; a.epi[1] = 0;
            a.wslot[2] = 1 + 3 * i + 2; a.bias[2] = b_l + i * DD; a.out[2] = pxl; a.epi[2] = 1;
            a.emit_split = 0;
            a.attn_w = 1; a.attn_slot = i & 1;
            a.attn_a = att_src + i * DD; a.attn_d = att_dst + i * DD;
            mma_gemm_k<<<gM3, 256, dynsmem>>>(pah, pal, a);
        }

        aggfuse_k<<<gW, 256>>>(pxh, pxl, ph,
                               ln_g + i * DD, ln_b + i * DD, betas + i * DD,
                               i == 0, i & 1);
    }

    gemm_small_k<OUTD><<<gG, 256>>>(pxloc, W_pred, b_pred, out);
}

// round 16
// speedup vs baseline: 1.0318x; 1.0050x over previous
#include <cuda_runtime.h>
#include <cuda_bf16.h>
#include <math.h>
#include <stdint.h>

#define NN   50000
#define EE   800000
#define DD   128
#define LL   3
#define OUTD 40
#define SB   512
#define NSB  ((NN + SB - 1) / SB)   // 98
#define PADW 20
#define SZW  (128 * PADW)           // words per smem tile (2560)

// ---------------- scratch (device globals; no allocation allowed) ----------------
__device__ float    g_h[NN * DD];
__device__ float    g_xh[NN * DD];
__device__ float    g_xl[NN * DD];
__device__ float    g_xlocal[NN * DD];
__device__ float    g_as[2 * NN];   // double-buffered attention logit accumulators
__device__ float    g_ad[2 * NN];
__device__ float    g_ew[EE];
__device__ int      g_deg[NN];
__device__ int      g_fill[NN];
__device__ int      g_rowptr[NN + 1];
__device__ int      g_esrc[EE];
__device__ int      g_src[EE];
__device__ int      g_dst[EE];
__device__ int      g_bsum[NSB];
__device__ int      g_boff[128];
// packed bf16 pairs (hi/lo) along k: [row][64 words]
__device__ uint32_t g_inh[NN * 64];
__device__ uint32_t g_inl[NN * 64];
__device__ uint32_t g_ah[NN * 64];
__device__ uint32_t g_al[NN * 64];
// pre-split weights: [wslot][n][64 words], 10 slots
__device__ uint32_t g_wsh[10 * 128 * 64];
__device__ uint32_t g_wsl[10 * 128 * 64];

__device__ __forceinline__ void bsplit(float v, uint32_t& h, uint32_t& l) {
    __nv_bfloat16 bh = __float2bfloat16_rn(v);
    float r = v - __bfloat162float(bh);
    __nv_bfloat16 bl = __float2bfloat16_rn(r);
    h = (uint32_t)__bfloat16_as_ushort(bh);
    l = (uint32_t)__bfloat16_as_ushort(bl);
}

__device__ __forceinline__ void cp16(void* dst_s, const void* src_g) {
    uint32_t d = (uint32_t)__cvta_generic_to_shared(dst_s);
    asm volatile("cp.async.cg.shared.global [%0], [%1], 16;" :: "r"(d), "l"(src_g));
}

// ---------------- edge decode + degree histogram (fused) ----------------
__global__ void decode_deg_k(const int* __restrict__ ei32) {
    bool is64 = (ei32[1] == 0 && ei32[3] == 0 && ei32[5] == 0 && ei32[7] == 0);
    int e = blockIdx.x * blockDim.x + threadIdx.x;
    if (e < EE) {
        int s, d;
        if (is64) {
            s = ei32[2 * (size_t)e];
            d = ei32[2 * ((size_t)EE + e)];
        } else {
            s = ei32[e];
            d = ei32[EE + e];
        }
        g_src[e] = s;
        g_dst[e] = d;
        atomicAdd(&g_deg[d], 1);
    }
}

__global__ void zero_k() {
    int i = blockIdx.x * blockDim.x + threadIdx.x;
    if (i < NN) {
        g_deg[i] = 0; g_fill[i] = 0;
        g_as[i] = 0.f; g_ad[i] = 0.f;
        g_as[NN + i] = 0.f; g_ad[NN + i] = 0.f;
    }
}

__global__ void pscan_k() {
    __shared__ int sh[SB];
    int t = threadIdx.x;
    int i = blockIdx.x * SB + t;
    int v = (i < NN) ? g_deg[i] : 0;
    sh[t] = v;
    __syncthreads();
    for (int o = 1; o < SB; o <<= 1) {
        int a = (t >= o) ? sh[t - o] : 0;
        __syncthreads();
        sh[t] += a;
        __syncthreads();
    }
    if (i < NN) g_rowptr[i] = sh[t] - v;
    if (t == SB - 1) g_bsum[blockIdx.x] = sh[t];
}

__global__ void bscan_k() {
    __shared__ int sh[128];
    int t = threadIdx.x;
    int v = (t < NSB) ? g_bsum[t] : 0;
    sh[t] = v;
    __syncthreads();
    for (int o = 1; o < 128; o <<= 1) {
        int a = (t >= o) ? sh[t - o] : 0;
        __syncthreads();
        sh[t] += a;
        __syncthreads();
    }
    g_boff[t] = sh[t] - v;
}

__global__ void addoff_k() {
    int i = blockIdx.x * blockDim.x + threadIdx.x;
    if (i < NN) g_rowptr[i] += g_boff[i / SB];
    if (i == 0) g_rowptr[NN] = EE;
}

__global__ void scat_k() {
    int e = blockIdx.x * blockDim.x + threadIdx.x;
    if (e < EE) {
        int d = g_dst[e];
        int p = g_rowptr[d] + atomicAdd(&g_fill[d], 1);
        g_esrc[p] = g_src[e];
    }
}

// ---------------- one-time weight split ----------------
__global__ void split_w_k(const float* __restrict__ W_in, const float* __restrict__ W_h,
                          const float* __restrict__ W_gat, const float* __restrict__ W_l) {
    int idx = blockIdx.x * blockDim.x + threadIdx.x;   // 10*64*128
    if (idx >= 10 * 64 * 128) return;
    int w   = idx >> 13;
    int kw  = (idx >> 7) & 63;
    int n   = idx & 127;
    const float* base;
    if (w == 0) base = W_in;
    else {
        int layer = (w - 1) / 3, t = (w - 1) % 3;
        base = (t == 0 ? W_h : t == 1 ? W_gat : W_l) + (size_t)layer * DD * DD;
    }
    float v0 = base[(size_t)(2 * kw) * DD + n];
    float v1 = base[(size_t)(2 * kw + 1) * DD + n];
    uint32_t h0, l0, h1, l1;
    bsplit(v0, h0, l0); bsplit(v1, h1, l1);
    g_wsh[(size_t)w * 8192 + n * 64 + kw] = h0 | (h1 << 16);
    g_wsl[(size_t)w * 8192 + n * 64 + kw] = l0 | (l1 << 16);
}

// ---------------- one-time input split ----------------
__global__ void split_x_k(const float* __restrict__ x) {
    int t = blockIdx.x * blockDim.x + threadIdx.x;     // NN*32
    if (t >= NN * 32) return;
    int row = t >> 5, q = t & 31;
    float4 v = ((const float4*)x)[(size_t)row * 32 + q];
    uint32_t hx, lx, hy, ly, hz, lz, hw, lw;
    bsplit(v.x, hx, lx); bsplit(v.y, hy, ly);
    bsplit(v.z, hz, lz); bsplit(v.w, hw, lw);
    size_t o = (size_t)row * 64 + 2 * q;
    g_inh[o]     = hx | (hy << 16);
    g_inh[o + 1] = hz | (hw << 16);
    g_inl[o]     = lx | (ly << 16);
    g_inl[o + 1] = lz | (lw << 16);
}

// ---------------- bf16x3 GEMM, cp.async double-buffered, fused attn logits ----------------
struct GemmArgs2 {
    int          wslot[3];
    const float* bias[3];
    float*       out[3];
    int          epi[3];     // 0 none, 1 bias, 2 bias+relu
    int          emit_split;
    int          attn_w;     // which w computes attention logits (-1 = none)
    int          attn_slot;  // accumulator slot (0/1)
    const float* attn_a;
    const float* attn_d;
};

extern __shared__ uint32_t smem_dyn[];

__global__ __launch_bounds__(256, 2)
void mma_gemm_k(const uint32_t* __restrict__ Ah, const uint32_t* __restrict__ Al,
                GemmArgs2 args) {
    const int tid  = threadIdx.x;
    const int lane = tid & 31;
    const int wid  = tid >> 5;
    const int wm   = (wid >> 1) * 32;
    const int wn   = (wid & 1) * 64;
    const int row0 = blockIdx.x * 128;
    const int w    = blockIdx.y;

    const uint32_t* Wh = g_wsh + (size_t)args.wslot[w] * 8192;
    const uint32_t* Wl = g_wsl + (size_t)args.wslot[w] * 8192;

    const int ar = lane >> 2;
    const int ac = lane & 3;

    float acc[2][8][4];
#pragma unroll
    for (int i = 0; i < 2; i++)
#pragma unroll
        for (int j = 0; j < 8; j++)
#pragma unroll
            for (int c = 0; c < 4; c++) acc[i][j][c] = 0.f;

    auto stage = [&](int kc, int s) {
        uint32_t* bAh = smem_dyn + s * 4 * SZW;
        uint32_t* bAl = bAh + SZW;
        uint32_t* bWh = bAl + SZW;
        uint32_t* bWl = bWh + SZW;
        const int kwc = kc >> 1;
#pragma unroll
        for (int t = tid; t < 512; t += 256) {
            int m = t >> 2, q = t & 3;
            int row = row0 + m;
            uint32_t* dh = &bAh[m * PADW + 4 * q];
            uint32_t* dl = &bAl[m * PADW + 4 * q];
            if (row < NN) {
                size_t o = (size_t)row * 64 + kwc + 4 * q;
                cp16(dh, &Ah[o]);
                cp16(dl, &Al[o]);
            } else {
                *(uint4*)dh = make_uint4(0, 0, 0, 0);
                *(uint4*)dl = make_uint4(0, 0, 0, 0);
            }
        }
#pragma unroll
        for (int t = tid; t < 512; t += 256) {
            int n = t >> 2, q = t & 3;
            size_t o = (size_t)n * 64 + kwc + 4 * q;
            cp16(&bWh[n * PADW + 4 * q], &Wh[o]);
            cp16(&bWl[n * PADW + 4 * q], &Wl[o]);
        }
        asm volatile("cp.async.commit_group;");
    };

    stage(0, 0);

#pragma unroll
    for (int c = 0; c < 4; c++) {
        if (c < 3) stage((c + 1) * 32, (c + 1) & 1);
        if (c < 3) asm volatile("cp.async.wait_group 1;");
        else       asm volatile("cp.async.wait_group 0;");
        __syncthreads();

        const uint32_t* bAh = smem_dyn + (c & 1) * 4 * SZW;
        const uint32_t* bAl = bAh + SZW;
        const uint32_t* bWh = bAl + SZW;
        const uint32_t* bWl = bWh + SZW;

#pragma unroll
        for (int s = 0; s < 2; s++) {
            const int kb = s * 8;
            uint32_t ah[2][4], al[2][4];
#pragma unroll
            for (int i = 0; i < 2; i++) {
                int m = wm + i * 16 + ar;
                ah[i][0] = bAh[m * PADW + kb + ac];
                ah[i][1] = bAh[(m + 8) * PADW + kb + ac];
                ah[i][2] = bAh[m * PADW + kb + ac + 4];
                ah[i][3] = bAh[(m + 8) * PADW + kb + ac + 4];
                al[i][0] = bAl[m * PADW + kb + ac];
                al[i][1] = bAl[(m + 8) * PADW + kb + ac];
                al[i][2] = bAl[m * PADW + kb + ac + 4];
                al[i][3] = bAl[(m + 8) * PADW + kb + ac + 4];
            }
#pragma unroll
            for (int j = 0; j < 8; j++) {
                int n = wn + j * 8 + ar;
                uint32_t bh0 = bWh[n * PADW + kb + ac];
                uint32_t bh1 = bWh[n * PADW + kb + ac + 4];
                uint32_t bl0 = bWl[n * PADW + kb + ac];
                uint32_t bl1 = bWl[n * PADW + kb + ac + 4];
#pragma unroll
                for (int i = 0; i < 2; i++) {
                    asm volatile(
                        "mma.sync.aligned.m16n8k16.row.col.f32.bf16.bf16.f32 "
                        "{%0,%1,%2,%3}, {%4,%5,%6,%7}, {%8,%9}, {%0,%1,%2,%3};"
                        : "+f"(acc[i][j][0]), "+f"(acc[i][j][1]),
                          "+f"(acc[i][j][2]), "+f"(acc[i][j][3])
                        : "r"(ah[i][0]), "r"(ah[i][1]), "r"(ah[i][2]), "r"(ah[i][3]),
                          "r"(bh0), "r"(bh1));
                    asm volatile(
                        "mma.sync.aligned.m16n8k16.row.col.f32.bf16.bf16.f32 "
                        "{%0,%1,%2,%3}, {%4,%5,%6,%7}, {%8,%9}, {%0,%1,%2,%3};"
                        : "+f"(acc[i][j][0]), "+f"(acc[i][j][1]),
                          "+f"(acc[i][j][2]), "+f"(acc[i][j][3])
                        : "r"(ah[i][0]), "r"(ah[i][1]), "r"(ah[i][2]), "r"(ah[i][3]),
                          "r"(bl0), "r"(bl1));
                    asm volatile(
                        "mma.sync.aligned.m16n8k16.row.col.f32.bf16.bf16.f32 "
                        "{%0,%1,%2,%3}, {%4,%5,%6,%7}, {%8,%9}, {%0,%1,%2,%3};"
                        : "+f"(acc[i][j][0]), "+f"(acc[i][j][1]),
                          "+f"(acc[i][j][2]), "+f"(acc[i][j][3])
                        : "r"(al[i][0]), "r"(al[i][1]), "r"(al[i][2]), "r"(al[i][3]),
                          "r"(bh0), "r"(bh1));
                }
            }
        }
        __syncthreads();
    }

    // ---- epilogue ----
    const int epi = args.epi[w];
    const float* bias = args.bias[w];
    float* out = args.out[w];
    const int emit = args.emit_split;
    const bool do_attn = (w == args.attn_w);
    float* asb = g_as + (size_t)args.attn_slot * NN;
    float* adb = g_ad + (size_t)args.attn_slot * NN;
    float ps[2] = {0.f, 0.f}, pd[2] = {0.f, 0.f};
    float ps2[2] = {0.f, 0.f}, pd2[2] = {0.f, 0.f};

#pragma unroll
    for (int i = 0; i < 2; i++) {
#pragma unroll
        for (int j = 0; j < 8; j++) {
            int cc = wn + j * 8 + ac * 2;
            float bx = 0.f, by = 0.f;
            if (epi >= 1) { bx = bias[cc]; by = bias[cc + 1]; }
            float c0 = acc[i][j][0] + bx, c1 = acc[i][j][1] + by;
            float c2 = acc[i][j][2] + bx, c3 = acc[i][j][3] + by;
            if (epi == 2) {
                c0 = fmaxf(c0, 0.f); c1 = fmaxf(c1, 0.f);
                c2 = fmaxf(c2, 0.f); c3 = fmaxf(c3, 0.f);
            }
            if (do_attn) {
                float a0 = args.attn_a[cc], a1 = args.attn_a[cc + 1];
                float d0 = args.attn_d[cc], d1 = args.attn_d[cc + 1];
                ps[i]  += c0 * a0 + c1 * a1;
                pd[i]  += c0 * d0 + c1 * d1;
                ps2[i] += c2 * a0 + c3 * a1;
                pd2[i] += c2 * d0 + c3 * d1;
            }
            int r0 = row0 + wm + i * 16 + ar;
            if (out) {
                if (r0 < NN)     *(float2*)&out[(size_t)r0 * DD + cc]       = make_float2(c0, c1);
                if (r0 + 8 < NN) *(float2*)&out[(size_t)(r0 + 8) * DD + cc] = make_float2(c2, c3);
            }
            if (emit) {
                uint32_t h0, l0, h1, l1;
                if (r0 < NN) {
                    bsplit(c0, h0, l0); bsplit(c1, h1, l1);
                    g_ah[(size_t)r0 * 64 + (cc >> 1)] = h0 | (h1 << 16);
                    g_al[(size_t)r0 * 64 + (cc >> 1)] = l0 | (l1 << 16);
                }
                if (r0 + 8 < NN) {
                    bsplit(c2, h0, l0); bsplit(c3, h1, l1);
                    g_ah[(size_t)(r0 + 8) * 64 + (cc >> 1)] = h0 | (h1 << 16);
                    g_al[(size_t)(r0 + 8) * 64 + (cc >> 1)] = l0 | (l1 << 16);
                }
            }
        }
    }

    if (do_attn) {
#pragma unroll
        for (int i = 0; i < 2; i++) {
#pragma unroll
            for (int o = 1; o <= 2; o <<= 1) {
                ps[i]  += __shfl_xor_sync(0xFFFFFFFFu, ps[i],  o);
                pd[i]  += __shfl_xor_sync(0xFFFFFFFFu, pd[i],  o);
                ps2[i] += __shfl_xor_sync(0xFFFFFFFFu, ps2[i], o);
                pd2[i] += __shfl_xor_sync(0xFFFFFFFFu, pd2[i], o);
            }
            if (ac == 0) {
                int r0 = row0 + wm + i * 16 + ar;
                if (r0 < NN) {
                    atomicAdd(&asb[r0], ps[i]);
                    atomicAdd(&adb[r0], pd[i]);
                }
                if (r0 + 8 < NN) {
                    atomicAdd(&asb[r0 + 8], ps2[i]);
                    atomicAdd(&adb[r0 + 8], pd2[i]);
                }
            }
        }
    }
}

// ---------------- small FFMA GEMM for the prediction head (NCOL=40) ----------------
template <int NCOL>
__global__ void gemm_small_k(const float* __restrict__ A, const float* __restrict__ W,
                             const float* __restrict__ bias, float* __restrict__ C) {
    constexpr int ROWS = 32;
    constexpr int KT   = 32;
    __shared__ float sA[ROWS][DD];
    __shared__ float sW[KT][NCOL];
    int tid  = threadIdx.x;
    int row0 = blockIdx.x * ROWS;

    {
        const float4* Af  = (const float4*)A;
        float4*       sAf = (float4*)sA;
#pragma unroll
        for (int i = 0; i < 4; i++) {
            int idx = tid + i * 256;
            int r = idx >> 5, c = idx & 31;
            float4 v = make_float4(0.f, 0.f, 0.f, 0.f);
            if (row0 + r < NN) v = Af[(size_t)(row0 + r) * 32 + c];
            sAf[idx] = v;
        }
    }

    int tx = tid & 31, ty = tid >> 5;
    const int col = tx * 4;
    float acc[4][4];
#pragma unroll
    for (int i = 0; i < 4; i++)
#pragma unroll
        for (int j = 0; j < 4; j++) acc[i][j] = 0.f;

    for (int kt = 0; kt < DD; kt += KT) {
        __syncthreads();
        {
            const float4* Wf  = (const float4*)(W + kt * NCOL);
            float4*       sWf = (float4*)sW;
            constexpr int T4 = KT * NCOL / 4;
            for (int i = tid; i < T4; i += 256) sWf[i] = Wf[i];
        }
        __syncthreads();
#pragma unroll
        for (int k = 0; k < KT; k++) {
            float4 wv = make_float4(0.f, 0.f, 0.f, 0.f);
            if (col < NCOL) wv = *(const float4*)&sW[k][col];
#pragma unroll
            for (int i = 0; i < 4; i++) {
                float a = sA[ty + i * 8][kt + k];
                acc[i][0] += a * wv.x;
                acc[i][1] += a * wv.y;
                acc[i][2] += a * wv.z;
                acc[i][3] += a * wv.w;
            }
        }
    }

    if (col < NCOL) {
        float4 bv = *(const float4*)&bias[col];
#pragma unroll
        for (int i = 0; i < 4; i++) {
            int row = row0 + ty + i * 8;
            if (row < NN) {
                float4 o;
                o.x = acc[i][0] + bv.x;
                o.y = acc[i][1] + bv.y;
                o.z = acc[i][2] + bv.z;
                o.w = acc[i][3] + bv.w;
                *(float4*)&C[(size_t)row * NCOL + col] = o;
            }
        }
    }
}

// ---------------- fused GAT aggregate + pointwise + emit split ----------------
// warp per destination node; online softmax caches post-leaky logits in g_ew.
__global__ void aggfuse_k(const float* __restrict__ xh,
                          const float* __restrict__ xlbuf, const float* __restrict__ hbuf,
                          const float* __restrict__ lng, const float* __restrict__ lnb,
                          const float* __restrict__ betas, int first, int slot) {
    int n    = (blockIdx.x * blockDim.x + threadIdx.x) >> 5;
    int lane = threadIdx.x & 31;
    if (n >= NN) return;
    const float* asb = g_as + (size_t)slot * NN;
    const float* adb = g_ad + (size_t)slot * NN;
    int s0 = g_rowptr[n], s1 = g_rowptr[n + 1];
    float adn = adb[n];

    // pass 1: online softmax over this lane's strided edges; cache logits
    float m = -1e30f, d = 0.f;
    for (int i = s0 + lane; i < s1; i += 32) {
        int s  = g_esrc[i];
        float e = asb[s] + adn;
        e = e > 0.f ? e : 0.2f * e;
        g_ew[i] = e;
        if (e > m) { d = d * __expf(m - e) + 1.f; m = e; }
        else       { d += __expf(e - m); }
    }
#pragma unroll
    for (int o = 16; o; o >>= 1) {
        float mo = __shfl_xor_sync(0xFFFFFFFFu, m, o);
        float do_ = __shfl_xor_sync(0xFFFFFFFFu, d, o);
        if (mo > m) { d = d * __expf(m - mo) + do_; m = mo; }
        else        { d += do_ * __expf(mo - m); }
    }
    float inv = 1.f / (d + 1e-16f);

    // pass 2: weighted gather of xh rows
    float4 ag = make_float4(0.f, 0.f, 0.f, 0.f);
    for (int base = s0; base < s1; base += 32) {
        int idx = base + lane;
        float w = 0.f;
        int   s = 0;
        if (idx < s1) {
            s = g_esrc[idx];
            w = __expf(g_ew[idx] - m) * inv;
        }
        int cnt = min(32, s1 - base);
        for (int j = 0; j < cnt; j++) {
            float wj = __shfl_sync(0xFFFFFFFFu, w, j);
            int   sj = __shfl_sync(0xFFFFFFFFu, s, j);
            float4 v = ((const float4*)(xh + (size_t)sj * DD))[lane];
            ag.x += wj * v.x; ag.y += wj * v.y;
            ag.z += wj * v.z; ag.w += wj * v.w;
        }
    }

    // ---- pointwise (agg stays in registers) ----
    size_t off = (size_t)n * DD;
    float4 xl = ((const float4*)(xlbuf + off))[lane];
    float4 xn;
    xn.x = fmaxf(ag.x + xl.x, 0.f);
    xn.y = fmaxf(ag.y + xl.y, 0.f);
    xn.z = fmaxf(ag.z + xl.z, 0.f);
    xn.w = fmaxf(ag.w + xl.w, 0.f);

    float4 hh = ((const float4*)(hbuf + off))[lane];
    float4 t;
    t.x = hh.x * xn.x; t.y = hh.y * xn.y; t.z = hh.z * xn.z; t.w = hh.w * xn.w;

    float sum = t.x + t.y + t.z + t.w;
#pragma unroll
    for (int o = 16; o; o >>= 1) sum += __shfl_xor_sync(0xFFFFFFFFu, sum, o);
    float mu = sum * (1.f / 128.f);

    float4 dc;
    dc.x = t.x - mu; dc.y = t.y - mu; dc.z = t.z - mu; dc.w = t.w - mu;
    float ss = dc.x * dc.x + dc.y * dc.y + dc.z * dc.z + dc.w * dc.w;
#pragma unroll
    for (int o = 16; o; o >>= 1) ss += __shfl_xor_sync(0xFFFFFFFFu, ss, o);
    float rs = rsqrtf(ss * (1.f / 128.f) + 1e-5f);

    float4 g  = ((const float4*)lng)[lane];
    float4 b  = ((const float4*)lnb)[lane];
    float4 be = ((const float4*)betas)[lane];
    be.x = 1.f / (1.f + __expf(-be.x));
    be.y = 1.f / (1.f + __expf(-be.y));
    be.z = 1.f / (1.f + __expf(-be.z));
    be.w = 1.f / (1.f + __expf(-be.w));

    float4 y;
    y.x = dc.x * rs * g.x + b.x;
    y.y = dc.y * rs * g.y + b.y;
    y.z = dc.z * rs * g.z + b.z;
    y.w = dc.w * rs * g.w + b.w;

    float4 xo;
    xo.x = (1.f - be.x) * y.x + be.x * xn.x;
    xo.y = (1.f - be.y) * y.y + be.y * xn.y;
    xo.z = (1.f - be.z) * y.z + be.z * xn.z;
    xo.w = (1.f - be.w) * y.w + be.w * xn.w;

    // emit bf16 split of new x
    {
        uint32_t hx, lx, hy, ly, hz, lz, hw, lw;
        bsplit(xo.x, hx, lx); bsplit(xo.y, hy, ly);
        bsplit(xo.z, hz, lz); bsplit(xo.w, hw, lw);
        size_t o2 = (size_t)n * 64 + 2 * lane;
        g_ah[o2]     = hx | (hy << 16);
        g_ah[o2 + 1] = hz | (hw << 16);
        g_al[o2]     = lx | (ly << 16);
        g_al[o2 + 1] = lz | (lw << 16);
    }

    if (first) {
        ((float4*)(g_xlocal + off))[lane] = xo;
    } else {
        float4 p = ((const float4*)(g_xlocal + off))[lane];
        p.x += xo.x; p.y += xo.y; p.z += xo.z; p.w += xo.w;
        ((float4*)(g_xlocal + off))[lane] = p;
    }

    // zero the OTHER attention slot (used by the next layer's GEMM)
    if (lane == 0) {
        int os = slot ^ 1;
        g_as[(size_t)os * NN + n] = 0.f;
        g_ad[(size_t)os * NN + n] = 0.f;
    }
}

// ---------------- host ----------------
extern "C" void kernel_launch(void* const* d_in, const int* in_sizes, int n_in,
                              void* d_out, int out_size) {
    const float* x       = (const float*)d_in[0];
    const int*   ei32    = (const int*)d_in[1];
    const float* W_in    = (const float*)d_in[2];
    const float* b_in    = (const float*)d_in[3];
    const float* W_h     = (const float*)d_in[4];
    const float* b_h     = (const float*)d_in[5];
    const float* W_gat   = (const float*)d_in[6];
    const float* att_src = (const float*)d_in[7];
    const float* att_dst = (const float*)d_in[8];
    const float* W_l     = (const float*)d_in[9];
    const float* b_l     = (const float*)d_in[10];
    const float* ln_g    = (const float*)d_in[11];
    const float* ln_b    = (const float*)d_in[12];
    const float* betas   = (const float*)d_in[13];
    const float* W_pred  = (const float*)d_in[14];
    const float* b_pred  = (const float*)d_in[15];
    float*       out     = (float*)d_out;

    float *ph, *pxh, *pxl, *pxloc;
    uint32_t *pinh, *pinl, *pah, *pal;
    cudaGetSymbolAddress((void**)&ph,    g_h);
    cudaGetSymbolAddress((void**)&pxh,   g_xh);
    cudaGetSymbolAddress((void**)&pxl,   g_xl);
    cudaGetSymbolAddress((void**)&pxloc, g_xlocal);
    cudaGetSymbolAddress((void**)&pinh,  g_inh);
    cudaGetSymbolAddress((void**)&pinl,  g_inl);
    cudaGetSymbolAddress((void**)&pah,   g_ah);
    cudaGetSymbolAddress((void**)&pal,   g_al);

    const int dynsmem = 2 * 4 * SZW * 4;   // 81920 bytes
    static cudaStream_t s_side = nullptr;
    static cudaEvent_t  ev_fork = nullptr, ev_join = nullptr;
    if (!s_side) {
        cudaFuncSetAttribute(mma_gemm_k, cudaFuncAttributeMaxDynamicSharedMemorySize, dynsmem);
        cudaStreamCreateWithFlags(&s_side, cudaStreamNonBlocking);
        cudaEventCreateWithFlags(&ev_fork, cudaEventDisableTiming);
        cudaEventCreateWithFlags(&ev_join, cudaEventDisableTiming);
    }

    dim3 gE((EE + 255) / 256);
    dim3 gN((NN + 255) / 256);
    dim3 gW((NN + 7) / 8);
    dim3 gG((NN + 31) / 32);
    dim3 gM((NN + 127) / 128, 1);
    dim3 gM3((NN + 127) / 128, 3);

    // zeroing on main (prereq for BOTH branches)
    zero_k<<<gN, 256>>>();

    // fork: CSR build on side stream
    cudaEventRecord(ev_fork, 0);
    cudaStreamWaitEvent(s_side, ev_fork, 0);
    decode_deg_k<<<gE, 256, 0, s_side>>>(ei32);
    pscan_k<<<NSB, SB, 0, s_side>>>();
    bscan_k<<<1, 128, 0, s_side>>>();
    addoff_k<<<gN, 256, 0, s_side>>>();
    scat_k<<<gE, 256, 0, s_side>>>();
    cudaEventRecord(ev_join, s_side);

    // main: splits + dense prologue (independent of CSR)
    split_w_k<<<(10 * 64 * 128 + 255) / 256, 256>>>(W_in, W_h, W_gat, W_l);
    split_x_k<<<(NN * 32 + 255) / 256, 256>>>(x);

    // input projection: x @ W_in + b_in -> split only
    {
        GemmArgs2 a{};
        a.wslot[0] = 0; a.bias[0] = b_in; a.out[0] = nullptr; a.epi[0] = 1;
        a.emit_split = 1; a.attn_w = -1;
        mma_gemm_k<<<gM, 256, dynsmem>>>(pinh, pinl, a);
    }

    // layer 0 GEMM is also CSR-independent
    {
        GemmArgs2 a{};
        a.wslot[0] = 1; a.bias[0] = b_h; a.out[0] = ph;  a.epi[0] = 2;
        a.wslot[1] = 2; a.bias[1] = nullptr; a.out[1] = pxh; a.epi[1] = 0;
        a.wslot[2] = 3; a.bias[2] = b_l; a.out[2] = pxl; a.epi[2] = 1;
        a.emit_split = 0;
        a.attn_w = 1; a.attn_slot = 0;
        a.attn_a = att_src; a.attn_d = att_dst;
        mma_gemm_k<<<gM3, 256, dynsmem>>>(pah, pal, a);
    }

    // join: aggfuse needs the CSR
    cudaStreamWaitEvent(0, ev_join, 0);

    for (int i = 0; i < LL; i++) {
        if (i > 0) {
            GemmArgs2 a{};
            a.wslot[0] = 1 + 3 * i;     a.bias[0] = b_h + i * DD; a.out[0] = ph;  a.epi[0] = 2;
            a.wslot[1] = 1 + 3 * i + 1; a.bias[1] = nullptr;      a.out[1] = pxh; a.epi[1] = 0;
            a.wslot[2] = 1 + 3 * i + 2; a.bias[2] = b_l + i * DD; a.out[2] = pxl; a.epi[2] = 1;
            a.emit_split = 0;
            a.attn_w = 1; a.attn_slot = i & 1;
            a.attn_a = att_src + i * DD; a.attn_d = att_dst + i * DD;
            mma_gemm_k<<<gM3, 256, dynsmem>>>(pah, pal, a);
        }

        aggfuse_k<<<gW, 256>>>(pxh, pxl, ph,
                               ln_g + i * DD, ln_b + i * DD, betas + i * DD,
                               i == 0, i & 1);
    }

    gemm_small_k<OUTD><<<gG, 256>>>(pxloc, W_pred, b_pred, out);
}